// round 1
// baseline (speedup 1.0000x reference)
#include <cuda_runtime.h>
#include <cuda_bf16.h>

#define B_      16
#define SQL     512
#define SKL     512
#define DMODEL  768
#define NH      12
#define HD_     64

// Scratch for projected Q/K/V (static device arrays: allocation-free, graph-safe)
__device__ float g_Q[B_ * SQL * DMODEL];
__device__ float g_K[B_ * SKL * DMODEL];
__device__ float g_V[B_ * SKL * DMODEL];

// ---------------------------------------------------------------------------
// GEMM: C[M,768] = A[M,768] @ W[768,768] + bias
// 128x128 block tile, BK=16, 256 threads, 8x8 per-thread micro-tile.
// sel picks output buffer (0=Q, 1=K, 2=V).
// ---------------------------------------------------------------------------
__global__ __launch_bounds__(256, 2)
void gemm_bias(const float* __restrict__ A, const float* __restrict__ W,
               const float* __restrict__ bias, int sel)
{
    const int N = DMODEL, K = DMODEL;
    __shared__ float As[16][128];   // [k][m]
    __shared__ float Bs[16][128];   // [k][n]

    float* __restrict__ C = (sel == 0) ? g_Q : ((sel == 1) ? g_K : g_V);

    int tid = threadIdx.x;
    int bm = blockIdx.y * 128;
    int bn = blockIdx.x * 128;
    int tx = tid & 15;      // col group
    int ty = tid >> 4;      // row group

    float acc[8][8];
#pragma unroll
    for (int i = 0; i < 8; i++)
#pragma unroll
        for (int j = 0; j < 8; j++) acc[i][j] = 0.f;

    int arow = tid >> 2;            // 0..63
    int acol = (tid & 3) << 2;      // 0,4,8,12
    int brow = tid >> 5;            // 0..7
    int bcol = (tid & 31) << 2;     // 0..124

    for (int k0 = 0; k0 < K; k0 += 16) {
        // load A tile (transposed into As[k][m])
#pragma unroll
        for (int h = 0; h < 2; h++) {
            float4 a4 = *(const float4*)(A + (long)(bm + arow + h * 64) * K + k0 + acol);
            As[acol + 0][arow + h * 64] = a4.x;
            As[acol + 1][arow + h * 64] = a4.y;
            As[acol + 2][arow + h * 64] = a4.z;
            As[acol + 3][arow + h * 64] = a4.w;
        }
        // load W tile (natural Bs[k][n])
#pragma unroll
        for (int h = 0; h < 2; h++) {
            *(float4*)&Bs[brow + h * 8][bcol] =
                *(const float4*)(W + (long)(k0 + brow + h * 8) * N + bn + bcol);
        }
        __syncthreads();

#pragma unroll
        for (int kk = 0; kk < 16; kk++) {
            float a[8], b[8];
#pragma unroll
            for (int i = 0; i < 8; i += 4)
                *(float4*)&a[i] = *(const float4*)&As[kk][ty * 8 + i];
#pragma unroll
            for (int j = 0; j < 8; j += 4)
                *(float4*)&b[j] = *(const float4*)&Bs[kk][tx * 8 + j];
#pragma unroll
            for (int i = 0; i < 8; i++)
#pragma unroll
                for (int j = 0; j < 8; j++)
                    acc[i][j] = fmaf(a[i], b[j], acc[i][j]);
        }
        __syncthreads();
    }

#pragma unroll
    for (int i = 0; i < 8; i++) {
        long row = bm + ty * 8 + i;
#pragma unroll
        for (int j = 0; j < 8; j += 4) {
            float4 o;
            o.x = acc[i][j + 0] + bias[bn + tx * 8 + j + 0];
            o.y = acc[i][j + 1] + bias[bn + tx * 8 + j + 1];
            o.z = acc[i][j + 2] + bias[bn + tx * 8 + j + 2];
            o.w = acc[i][j + 3] + bias[bn + tx * 8 + j + 3];
            *(float4*)&C[row * N + bn + tx * 8 + j] = o;
        }
    }
}

// ---------------------------------------------------------------------------
// Fused attention: block = (b, h, 64-row q-tile). Streams K/V in 64-row tiles,
// online softmax, 4x4 per-thread micro-tile. smem = exactly 48KB.
// ---------------------------------------------------------------------------
__global__ __launch_bounds__(256)
void attn_kernel(float* __restrict__ Out)
{
    __shared__ float Qt[64 * 64];   // [d][r]  (Q transposed, pre-scaled)
    __shared__ float KP[64 * 64];   // phase 1: Kt[d][c]; phase 2: Pt[c][r]
    __shared__ float Vs[64 * 64];   // [c][d]

    int tid = threadIdx.x;
    int b  = blockIdx.z;
    int h  = blockIdx.y;
    int q0 = blockIdx.x * 64;

    int tc = tid & 15;   // col group (4 cols)
    int tr = tid >> 4;   // row group (4 rows)

    // --- load Q tile transposed & pre-scaled by 1/sqrt(64) ---
    {
        int row = tid >> 2;             // 0..63
        int c0  = (tid & 3) * 16;       // 0,16,32,48
        const float* src = g_Q + ((long)b * SQL + q0 + row) * DMODEL + h * HD_ + c0;
#pragma unroll
        for (int u = 0; u < 4; u++) {
            float4 v = *(const float4*)(src + u * 4);
            Qt[(c0 + u * 4 + 0) * 64 + row] = v.x * 0.125f;
            Qt[(c0 + u * 4 + 1) * 64 + row] = v.y * 0.125f;
            Qt[(c0 + u * 4 + 2) * 64 + row] = v.z * 0.125f;
            Qt[(c0 + u * 4 + 3) * 64 + row] = v.w * 0.125f;
        }
    }

    float m[4], l[4], o[4][4];
#pragma unroll
    for (int i = 0; i < 4; i++) {
        m[i] = -1e30f; l[i] = 0.f;
#pragma unroll
        for (int j = 0; j < 4; j++) o[i][j] = 0.f;
    }

    for (int t = 0; t < 8; t++) {
        int k0 = t * 64;
        // --- load K tile (transposed) and V tile (natural) ---
        {
            int row = tid >> 2;
            int c0  = (tid & 3) * 16;
            const float* ksrc = g_K + ((long)b * SKL + k0 + row) * DMODEL + h * HD_ + c0;
            const float* vsrc = g_V + ((long)b * SKL + k0 + row) * DMODEL + h * HD_ + c0;
#pragma unroll
            for (int u = 0; u < 4; u++) {
                float4 kv = *(const float4*)(ksrc + u * 4);
                KP[(c0 + u * 4 + 0) * 64 + row] = kv.x;
                KP[(c0 + u * 4 + 1) * 64 + row] = kv.y;
                KP[(c0 + u * 4 + 2) * 64 + row] = kv.z;
                KP[(c0 + u * 4 + 3) * 64 + row] = kv.w;
                *(float4*)&Vs[row * 64 + c0 + u * 4] = *(const float4*)(vsrc + u * 4);
            }
        }
        __syncthreads();

        // --- S = Q K^T (this thread: rows tr*4+i, cols tc*4+j) ---
        float acc[4][4];
#pragma unroll
        for (int i = 0; i < 4; i++)
#pragma unroll
            for (int j = 0; j < 4; j++) acc[i][j] = 0.f;

#pragma unroll 8
        for (int d = 0; d < 64; d++) {
            float4 q4 = *(const float4*)&Qt[d * 64 + tr * 4];
            float4 k4 = *(const float4*)&KP[d * 64 + tc * 4];
            float qa[4] = { q4.x, q4.y, q4.z, q4.w };
            float ka[4] = { k4.x, k4.y, k4.z, k4.w };
#pragma unroll
            for (int i = 0; i < 4; i++)
#pragma unroll
                for (int j = 0; j < 4; j++)
                    acc[i][j] = fmaf(qa[i], ka[j], acc[i][j]);
        }

        // --- online softmax (row reduction across the 16 tc-lanes) ---
        float mt[4];
#pragma unroll
        for (int i = 0; i < 4; i++) {
            mt[i] = acc[i][0];
#pragma unroll
            for (int j = 1; j < 4; j++) mt[i] = fmaxf(mt[i], acc[i][j]);
        }
#pragma unroll
        for (int mask = 1; mask <= 8; mask <<= 1)
#pragma unroll
            for (int i = 0; i < 4; i++)
                mt[i] = fmaxf(mt[i], __shfl_xor_sync(0xffffffffu, mt[i], mask));

        float corr[4], ls[4];
#pragma unroll
        for (int i = 0; i < 4; i++) {
            float mn = fmaxf(m[i], mt[i]);
            corr[i] = __expf(m[i] - mn);
            m[i] = mn;
            float s = 0.f;
#pragma unroll
            for (int j = 0; j < 4; j++) {
                acc[i][j] = __expf(acc[i][j] - mn);
                s += acc[i][j];
            }
            ls[i] = s;
        }
#pragma unroll
        for (int mask = 1; mask <= 8; mask <<= 1)
#pragma unroll
            for (int i = 0; i < 4; i++)
                ls[i] += __shfl_xor_sync(0xffffffffu, ls[i], mask);
#pragma unroll
        for (int i = 0; i < 4; i++) {
            l[i] = l[i] * corr[i] + ls[i];
#pragma unroll
            for (int j = 0; j < 4; j++) o[i][j] *= corr[i];
        }

        __syncthreads();    // everyone done reading Kt before overwrite with P

        // --- write P into KP as Pt[c][r] ---
#pragma unroll
        for (int j = 0; j < 4; j++)
#pragma unroll
            for (int i = 0; i < 4; i++)
                KP[(tc * 4 + j) * 64 + tr * 4 + i] = acc[i][j];
        __syncwarp();       // P rows needed by this thread are produced within its own warp

        // --- O += P V ---
#pragma unroll 4
        for (int c = 0; c < 64; c++) {
            float p0 = KP[c * 64 + tr * 4 + 0];
            float p1 = KP[c * 64 + tr * 4 + 1];
            float p2 = KP[c * 64 + tr * 4 + 2];
            float p3 = KP[c * 64 + tr * 4 + 3];
            float4 v4 = *(const float4*)&Vs[c * 64 + tc * 4];
            o[0][0] = fmaf(p0, v4.x, o[0][0]); o[0][1] = fmaf(p0, v4.y, o[0][1]);
            o[0][2] = fmaf(p0, v4.z, o[0][2]); o[0][3] = fmaf(p0, v4.w, o[0][3]);
            o[1][0] = fmaf(p1, v4.x, o[1][0]); o[1][1] = fmaf(p1, v4.y, o[1][1]);
            o[1][2] = fmaf(p1, v4.z, o[1][2]); o[1][3] = fmaf(p1, v4.w, o[1][3]);
            o[2][0] = fmaf(p2, v4.x, o[2][0]); o[2][1] = fmaf(p2, v4.y, o[2][1]);
            o[2][2] = fmaf(p2, v4.z, o[2][2]); o[2][3] = fmaf(p2, v4.w, o[2][3]);
            o[3][0] = fmaf(p3, v4.x, o[3][0]); o[3][1] = fmaf(p3, v4.y, o[3][1]);
            o[3][2] = fmaf(p3, v4.z, o[3][2]); o[3][3] = fmaf(p3, v4.w, o[3][3]);
        }
        __syncthreads();    // before next tile's loads overwrite KP/Vs
    }

    // --- normalize and write out: out[b, q, h*64+d] ---
#pragma unroll
    for (int i = 0; i < 4; i++) {
        float inv = 1.f / l[i];
        float4 ov;
        ov.x = o[i][0] * inv;
        ov.y = o[i][1] * inv;
        ov.z = o[i][2] * inv;
        ov.w = o[i][3] * inv;
        *(float4*)&Out[((long)b * SQL + q0 + tr * 4 + i) * DMODEL + h * HD_ + tc * 4] = ov;
    }
}

// ---------------------------------------------------------------------------
extern "C" void kernel_launch(void* const* d_in, const int* in_sizes, int n_in,
                              void* d_out, int out_size)
{
    const float* hidden  = (const float*)d_in[0];
    const float* context = (const float*)d_in[1];
    const float* Wq = (const float*)d_in[2];
    const float* bq = (const float*)d_in[3];
    const float* Wk = (const float*)d_in[4];
    const float* bk = (const float*)d_in[5];
    const float* Wv = (const float*)d_in[6];
    const float* bv = (const float*)d_in[7];
    float* out = (float*)d_out;

    dim3 ggrid(DMODEL / 128, (B_ * SQL) / 128);   // (6, 64)
    gemm_bias<<<ggrid, 256>>>(hidden,  Wq, bq, 0);
    gemm_bias<<<ggrid, 256>>>(context, Wk, bk, 1);
    gemm_bias<<<ggrid, 256>>>(context, Wv, bv, 2);

    dim3 agrid(SQL / 64, NH, B_);                 // (8, 12, 16)
    attn_kernel<<<agrid, 256>>>(out);
}

// round 3
// speedup vs baseline: 1.2621x; 1.2621x over previous
#include <cuda_runtime.h>
#include <cuda_bf16.h>
#include <cstdint>

#define B_      16
#define SQL     512
#define SKL     512
#define DMODEL  768
#define NH      12
#define HD_     64

// ---------------------------------------------------------------------------
// Static device scratch (allocation-free, graph-safe)
// ---------------------------------------------------------------------------
__device__ float g_Q[B_ * SQL * DMODEL];
__device__ float g_K[B_ * SKL * DMODEL];
__device__ float g_V[B_ * SKL * DMODEL];
__device__ float g_WT[3][DMODEL * DMODEL];   // transposed weights [n][k]

// ---------------------------------------------------------------------------
// Weight transpose: g_WT[sel][n*768+k] = W[k*768+n]
// ---------------------------------------------------------------------------
__global__ void transpose_w(const float* __restrict__ Wq, const float* __restrict__ Wk,
                            const float* __restrict__ Wv)
{
    __shared__ float tile[32][33];
    const float* W = (blockIdx.z == 0) ? Wq : ((blockIdx.z == 1) ? Wk : Wv);
    float* WT = g_WT[blockIdx.z];
    int x = blockIdx.x * 32 + threadIdx.x;
    int y = blockIdx.y * 32 + threadIdx.y;
#pragma unroll
    for (int j = 0; j < 32; j += 8)
        tile[threadIdx.y + j][threadIdx.x] = W[(y + j) * DMODEL + x];
    __syncthreads();
    x = blockIdx.y * 32 + threadIdx.x;
    y = blockIdx.x * 32 + threadIdx.y;
#pragma unroll
    for (int j = 0; j < 32; j += 8)
        WT[(y + j) * DMODEL + x] = tile[threadIdx.x][threadIdx.y + j];
}

// ---------------------------------------------------------------------------
// bf16 m16n8k16 mma (arch-portable HMMA; compiles at sm_100)
// ---------------------------------------------------------------------------
__device__ __forceinline__ void mma16816(float* d, const uint32_t* a, const uint32_t* b)
{
    asm volatile(
        "mma.sync.aligned.m16n8k16.row.col.f32.bf16.bf16.f32 "
        "{%0,%1,%2,%3}, {%4,%5,%6,%7}, {%8,%9}, {%0,%1,%2,%3};"
        : "+f"(d[0]), "+f"(d[1]), "+f"(d[2]), "+f"(d[3])
        : "r"(a[0]), "r"(a[1]), "r"(a[2]), "r"(a[3]), "r"(b[0]), "r"(b[1]));
}

__device__ __forceinline__ void split_bf16(float x, __nv_bfloat16& hi, __nv_bfloat16& lo)
{
    hi = __float2bfloat16_rn(x);
    lo = __float2bfloat16_rn(x - __bfloat162float(hi));
}

// ---------------------------------------------------------------------------
// Projection GEMM via 3-term bf16-split mma.sync:
//   C[8192,768] = A[8192,768] @ WT[768,768]^T + bias   (sel picks C buffer)
// CTA tile 128x128, K-chunk 16, double-buffered, 48KB static smem.
// 8 warps = 2(m) x 4(n), warp tile 64x32, per warp 4x4 m16n8k16 frags.
// ---------------------------------------------------------------------------
#define APAD 24    // bf16 row stride (16 data + 8 pad) -> conflict-free frag LDS

__global__ __launch_bounds__(256)
void proj_mma(const float* __restrict__ A, const float* __restrict__ bias, int sel)
{
    __shared__ __nv_bfloat16 Ah[2][128][APAD];
    __shared__ __nv_bfloat16 Al[2][128][APAD];
    __shared__ __nv_bfloat16 Bh[2][128][APAD];
    __shared__ __nv_bfloat16 Bl[2][128][APAD];

    float* __restrict__ C = (sel == 0) ? g_Q : ((sel == 1) ? g_K : g_V);
    const float* __restrict__ WT = g_WT[sel];

    const int tid = threadIdx.x;
    const int lane = tid & 31;
    const int wid = tid >> 5;
    const int warp_m = wid >> 2;   // 0..1 -> 64 rows
    const int warp_n = wid & 3;    // 0..3 -> 32 cols
    const int bm = blockIdx.y * 128;
    const int bn = blockIdx.x * 128;

    // loader mapping: 2 threads per row, 8 floats each
    const int lr = tid >> 1;            // 0..127
    const int lc = (tid & 1) * 8;       // 0 or 8

    // fragment mapping
    const int fr = lane >> 2;           // 0..7
    const int fk = (lane & 3) * 2;      // 0,2,4,6

    float acc[4][4][4];
#pragma unroll
    for (int i = 0; i < 4; i++)
#pragma unroll
        for (int j = 0; j < 4; j++)
#pragma unroll
            for (int r = 0; r < 4; r++) acc[i][j][r] = 0.f;

    const int NCH = DMODEL / 16;   // 48

    // prefetch chunk 0
    float4 pa0, pa1, pb0, pb1;
    {
        const float* ap = A  + (size_t)(bm + lr) * DMODEL + lc;
        const float* bp = WT + (size_t)(bn + lr) * DMODEL + lc;
        pa0 = *(const float4*)(ap + 0);
        pa1 = *(const float4*)(ap + 4);
        pb0 = *(const float4*)(bp + 0);
        pb1 = *(const float4*)(bp + 4);
    }

    for (int c = 0; c < NCH; c++) {
        const int buf = c & 1;
        // convert + store prefetched chunk
        {
            float av[8] = { pa0.x, pa0.y, pa0.z, pa0.w, pa1.x, pa1.y, pa1.z, pa1.w };
            float bv[8] = { pb0.x, pb0.y, pb0.z, pb0.w, pb1.x, pb1.y, pb1.z, pb1.w };
#pragma unroll
            for (int i = 0; i < 8; i += 2) {
                __nv_bfloat162 h2, l2;
                split_bf16(av[i],     h2.x, l2.x);
                split_bf16(av[i + 1], h2.y, l2.y);
                *(__nv_bfloat162*)&Ah[buf][lr][lc + i] = h2;
                *(__nv_bfloat162*)&Al[buf][lr][lc + i] = l2;
                split_bf16(bv[i],     h2.x, l2.x);
                split_bf16(bv[i + 1], h2.y, l2.y);
                *(__nv_bfloat162*)&Bh[buf][lr][lc + i] = h2;
                *(__nv_bfloat162*)&Bl[buf][lr][lc + i] = l2;
            }
        }
        // prefetch next chunk
        if (c + 1 < NCH) {
            const float* ap = A  + (size_t)(bm + lr) * DMODEL + (c + 1) * 16 + lc;
            const float* bp = WT + (size_t)(bn + lr) * DMODEL + (c + 1) * 16 + lc;
            pa0 = *(const float4*)(ap + 0);
            pa1 = *(const float4*)(ap + 4);
            pb0 = *(const float4*)(bp + 0);
            pb1 = *(const float4*)(bp + 4);
        }
        __syncthreads();

        // load fragments
        uint32_t fah[4][4], fal[4][4], fbh[4][2], fbl[4][2];
#pragma unroll
        for (int mt = 0; mt < 4; mt++) {
            int r = warp_m * 64 + mt * 16 + fr;
            fah[mt][0] = *(const uint32_t*)&Ah[buf][r][fk];
            fah[mt][1] = *(const uint32_t*)&Ah[buf][r + 8][fk];
            fah[mt][2] = *(const uint32_t*)&Ah[buf][r][fk + 8];
            fah[mt][3] = *(const uint32_t*)&Ah[buf][r + 8][fk + 8];
            fal[mt][0] = *(const uint32_t*)&Al[buf][r][fk];
            fal[mt][1] = *(const uint32_t*)&Al[buf][r + 8][fk];
            fal[mt][2] = *(const uint32_t*)&Al[buf][r][fk + 8];
            fal[mt][3] = *(const uint32_t*)&Al[buf][r + 8][fk + 8];
        }
#pragma unroll
        for (int nt = 0; nt < 4; nt++) {
            int n = warp_n * 32 + nt * 8 + fr;
            fbh[nt][0] = *(const uint32_t*)&Bh[buf][n][fk];
            fbh[nt][1] = *(const uint32_t*)&Bh[buf][n][fk + 8];
            fbl[nt][0] = *(const uint32_t*)&Bl[buf][n][fk];
            fbl[nt][1] = *(const uint32_t*)&Bl[buf][n][fk + 8];
        }

#pragma unroll
        for (int mt = 0; mt < 4; mt++)
#pragma unroll
            for (int nt = 0; nt < 4; nt++) {
                mma16816(acc[mt][nt], fah[mt], fbh[nt]);
                mma16816(acc[mt][nt], fah[mt], fbl[nt]);
                mma16816(acc[mt][nt], fal[mt], fbh[nt]);
            }
        // NOTE: no second sync needed — next iteration stores into the OTHER
        // buffer; its previous readers finished before the sync above.
    }

    // epilogue: c0,c1 -> (fr, fk/fk+1); c2,c3 -> (fr+8, ...)
#pragma unroll
    for (int mt = 0; mt < 4; mt++) {
#pragma unroll
        for (int nt = 0; nt < 4; nt++) {
            int rg = bm + warp_m * 64 + mt * 16 + fr;
            int cg = bn + warp_n * 32 + nt * 8 + fk;
            float b0 = __ldg(bias + cg), b1 = __ldg(bias + cg + 1);
            float2 o0 = { acc[mt][nt][0] + b0, acc[mt][nt][1] + b1 };
            float2 o1 = { acc[mt][nt][2] + b0, acc[mt][nt][3] + b1 };
            *(float2*)&C[(size_t)rg * DMODEL + cg] = o0;
            *(float2*)&C[(size_t)(rg + 8) * DMODEL + cg] = o1;
        }
    }
}

// ---------------------------------------------------------------------------
// Fused attention (unchanged from round 1): block = (b, h, 64-row q-tile)
// ---------------------------------------------------------------------------
__global__ __launch_bounds__(256)
void attn_kernel(float* __restrict__ Out)
{
    __shared__ float Qt[64 * 64];
    __shared__ float KP[64 * 64];
    __shared__ float Vs[64 * 64];

    int tid = threadIdx.x;
    int b  = blockIdx.z;
    int h  = blockIdx.y;
    int q0 = blockIdx.x * 64;

    int tc = tid & 15;
    int tr = tid >> 4;

    {
        int row = tid >> 2;
        int c0  = (tid & 3) * 16;
        const float* src = g_Q + ((long)b * SQL + q0 + row) * DMODEL + h * HD_ + c0;
#pragma unroll
        for (int u = 0; u < 4; u++) {
            float4 v = *(const float4*)(src + u * 4);
            Qt[(c0 + u * 4 + 0) * 64 + row] = v.x * 0.125f;
            Qt[(c0 + u * 4 + 1) * 64 + row] = v.y * 0.125f;
            Qt[(c0 + u * 4 + 2) * 64 + row] = v.z * 0.125f;
            Qt[(c0 + u * 4 + 3) * 64 + row] = v.w * 0.125f;
        }
    }

    float m[4], l[4], o[4][4];
#pragma unroll
    for (int i = 0; i < 4; i++) {
        m[i] = -1e30f; l[i] = 0.f;
#pragma unroll
        for (int j = 0; j < 4; j++) o[i][j] = 0.f;
    }

    for (int t = 0; t < 8; t++) {
        int k0 = t * 64;
        {
            int row = tid >> 2;
            int c0  = (tid & 3) * 16;
            const float* ksrc = g_K + ((long)b * SKL + k0 + row) * DMODEL + h * HD_ + c0;
            const float* vsrc = g_V + ((long)b * SKL + k0 + row) * DMODEL + h * HD_ + c0;
#pragma unroll
            for (int u = 0; u < 4; u++) {
                float4 kv = *(const float4*)(ksrc + u * 4);
                KP[(c0 + u * 4 + 0) * 64 + row] = kv.x;
                KP[(c0 + u * 4 + 1) * 64 + row] = kv.y;
                KP[(c0 + u * 4 + 2) * 64 + row] = kv.z;
                KP[(c0 + u * 4 + 3) * 64 + row] = kv.w;
                *(float4*)&Vs[row * 64 + c0 + u * 4] = *(const float4*)(vsrc + u * 4);
            }
        }
        __syncthreads();

        float acc[4][4];
#pragma unroll
        for (int i = 0; i < 4; i++)
#pragma unroll
            for (int j = 0; j < 4; j++) acc[i][j] = 0.f;

#pragma unroll 8
        for (int d = 0; d < 64; d++) {
            float4 q4 = *(const float4*)&Qt[d * 64 + tr * 4];
            float4 k4 = *(const float4*)&KP[d * 64 + tc * 4];
            float qa[4] = { q4.x, q4.y, q4.z, q4.w };
            float ka[4] = { k4.x, k4.y, k4.z, k4.w };
#pragma unroll
            for (int i = 0; i < 4; i++)
#pragma unroll
                for (int j = 0; j < 4; j++)
                    acc[i][j] = fmaf(qa[i], ka[j], acc[i][j]);
        }

        float mt[4];
#pragma unroll
        for (int i = 0; i < 4; i++) {
            mt[i] = acc[i][0];
#pragma unroll
            for (int j = 1; j < 4; j++) mt[i] = fmaxf(mt[i], acc[i][j]);
        }
#pragma unroll
        for (int mask = 1; mask <= 8; mask <<= 1)
#pragma unroll
            for (int i = 0; i < 4; i++)
                mt[i] = fmaxf(mt[i], __shfl_xor_sync(0xffffffffu, mt[i], mask));

        float corr[4], ls[4];
#pragma unroll
        for (int i = 0; i < 4; i++) {
            float mn = fmaxf(m[i], mt[i]);
            corr[i] = __expf(m[i] - mn);
            m[i] = mn;
            float s = 0.f;
#pragma unroll
            for (int j = 0; j < 4; j++) {
                acc[i][j] = __expf(acc[i][j] - mn);
                s += acc[i][j];
            }
            ls[i] = s;
        }
#pragma unroll
        for (int mask = 1; mask <= 8; mask <<= 1)
#pragma unroll
            for (int i = 0; i < 4; i++)
                ls[i] += __shfl_xor_sync(0xffffffffu, ls[i], mask);
#pragma unroll
        for (int i = 0; i < 4; i++) {
            l[i] = l[i] * corr[i] + ls[i];
#pragma unroll
            for (int j = 0; j < 4; j++) o[i][j] *= corr[i];
        }

        __syncthreads();

#pragma unroll
        for (int j = 0; j < 4; j++)
#pragma unroll
            for (int i = 0; i < 4; i++)
                KP[(tc * 4 + j) * 64 + tr * 4 + i] = acc[i][j];
        __syncwarp();

#pragma unroll 4
        for (int c = 0; c < 64; c++) {
            float p0 = KP[c * 64 + tr * 4 + 0];
            float p1 = KP[c * 64 + tr * 4 + 1];
            float p2 = KP[c * 64 + tr * 4 + 2];
            float p3 = KP[c * 64 + tr * 4 + 3];
            float4 v4 = *(const float4*)&Vs[c * 64 + tc * 4];
            o[0][0] = fmaf(p0, v4.x, o[0][0]); o[0][1] = fmaf(p0, v4.y, o[0][1]);
            o[0][2] = fmaf(p0, v4.z, o[0][2]); o[0][3] = fmaf(p0, v4.w, o[0][3]);
            o[1][0] = fmaf(p1, v4.x, o[1][0]); o[1][1] = fmaf(p1, v4.y, o[1][1]);
            o[1][2] = fmaf(p1, v4.z, o[1][2]); o[1][3] = fmaf(p1, v4.w, o[1][3]);
            o[2][0] = fmaf(p2, v4.x, o[2][0]); o[2][1] = fmaf(p2, v4.y, o[2][1]);
            o[2][2] = fmaf(p2, v4.z, o[2][2]); o[2][3] = fmaf(p2, v4.w, o[2][3]);
            o[3][0] = fmaf(p3, v4.x, o[3][0]); o[3][1] = fmaf(p3, v4.y, o[3][1]);
            o[3][2] = fmaf(p3, v4.z, o[3][2]); o[3][3] = fmaf(p3, v4.w, o[3][3]);
        }
        __syncthreads();
    }

#pragma unroll
    for (int i = 0; i < 4; i++) {
        float inv = 1.f / l[i];
        float4 ov;
        ov.x = o[i][0] * inv;
        ov.y = o[i][1] * inv;
        ov.z = o[i][2] * inv;
        ov.w = o[i][3] * inv;
        *(float4*)&Out[((long)b * SQL + q0 + tr * 4 + i) * DMODEL + h * HD_ + tc * 4] = ov;
    }
}

// ---------------------------------------------------------------------------
extern "C" void kernel_launch(void* const* d_in, const int* in_sizes, int n_in,
                              void* d_out, int out_size)
{
    const float* hidden  = (const float*)d_in[0];
    const float* context = (const float*)d_in[1];
    const float* Wq = (const float*)d_in[2];
    const float* bq = (const float*)d_in[3];
    const float* Wk = (const float*)d_in[4];
    const float* bk = (const float*)d_in[5];
    const float* Wv = (const float*)d_in[6];
    const float* bv = (const float*)d_in[7];
    float* out = (float*)d_out;

    dim3 tgrid(DMODEL / 32, DMODEL / 32, 3);
    transpose_w<<<tgrid, dim3(32, 8)>>>(Wq, Wk, Wv);

    dim3 pgrid(DMODEL / 128, (B_ * SQL) / 128);   // (6, 64)
    proj_mma<<<pgrid, 256>>>(hidden,  bq, 0);
    proj_mma<<<pgrid, 256>>>(context, bk, 1);
    proj_mma<<<pgrid, 256>>>(context, bv, 2);

    dim3 agrid(SQL / 64, NH, B_);                 // (8, 12, 16)
    attn_kernel<<<agrid, 256>>>(out);
}

// round 4
// speedup vs baseline: 1.4614x; 1.1579x over previous
#include <cuda_runtime.h>
#include <cuda_bf16.h>
#include <cstdint>

#define B_      16
#define SQL     512
#define SKL     512
#define DMODEL  768
#define NH      12
#define HD_     64

// ---------------------------------------------------------------------------
// Static device scratch (allocation-free, graph-safe)
// ---------------------------------------------------------------------------
__device__ float g_Q[B_ * SQL * DMODEL];
__device__ float g_K[B_ * SKL * DMODEL];
__device__ float g_V[B_ * SKL * DMODEL];

// pre-split bf16 inputs (hi/lo) and transposed+split weights
__device__ __nv_bfloat16 g_Hh[B_ * SQL * DMODEL];   // hidden hi
__device__ __nv_bfloat16 g_Hl[B_ * SQL * DMODEL];   // hidden lo
__device__ __nv_bfloat16 g_Ch[B_ * SKL * DMODEL];   // context hi
__device__ __nv_bfloat16 g_Cl[B_ * SKL * DMODEL];   // context lo
__device__ __nv_bfloat16 g_WTh[3][DMODEL * DMODEL]; // W^T hi  [n][k]
__device__ __nv_bfloat16 g_WTl[3][DMODEL * DMODEL]; // W^T lo  [n][k]

// ---------------------------------------------------------------------------
__device__ __forceinline__ uint32_t smem_u32(const void* p) {
    uint32_t a;
    asm("{ .reg .u64 t; cvta.to.shared.u64 t, %1; cvt.u32.u64 %0, t; }" : "=r"(a) : "l"(p));
    return a;
}
#define CP_ASYNC16(dst, src) \
    asm volatile("cp.async.cg.shared.global [%0], [%1], 16;" :: "r"(dst), "l"(src))
#define CP_COMMIT() asm volatile("cp.async.commit_group;" ::: "memory")
#define CP_WAIT1()  asm volatile("cp.async.wait_group 1;" ::: "memory")

__device__ __forceinline__ void mma16816(float* d, const uint32_t* a, const uint32_t* b)
{
    asm volatile(
        "mma.sync.aligned.m16n8k16.row.col.f32.bf16.bf16.f32 "
        "{%0,%1,%2,%3}, {%4,%5,%6,%7}, {%8,%9}, {%0,%1,%2,%3};"
        : "+f"(d[0]), "+f"(d[1]), "+f"(d[2]), "+f"(d[3])
        : "r"(a[0]), "r"(a[1]), "r"(a[2]), "r"(a[3]), "r"(b[0]), "r"(b[1]));
}

__device__ __forceinline__ void split_bf16(float x, __nv_bfloat16& hi, __nv_bfloat16& lo)
{
    hi = __float2bfloat16_rn(x);
    lo = __float2bfloat16_rn(x - __bfloat162float(hi));
}

// ---------------------------------------------------------------------------
// Pre-split input: X fp32 -> Xh + Xl bf16
// ---------------------------------------------------------------------------
__global__ void split_in(const float* __restrict__ X,
                         __nv_bfloat16* __restrict__ Xh,
                         __nv_bfloat16* __restrict__ Xl)
{
    int i = (blockIdx.x * blockDim.x + threadIdx.x) * 4;
    float4 v = *(const float4*)(X + i);
    __nv_bfloat162 h0, h1, l0, l1;
    split_bf16(v.x, h0.x, l0.x); split_bf16(v.y, h0.y, l0.y);
    split_bf16(v.z, h1.x, l1.x); split_bf16(v.w, h1.y, l1.y);
    *(__nv_bfloat162*)(Xh + i)     = h0;
    *(__nv_bfloat162*)(Xh + i + 2) = h1;
    *(__nv_bfloat162*)(Xl + i)     = l0;
    *(__nv_bfloat162*)(Xl + i + 2) = l1;
}

// ---------------------------------------------------------------------------
// Transpose + split weights: g_WTh/l[sel][n*768+k] = split(W[k*768+n])
// ---------------------------------------------------------------------------
__global__ void transpose_w(const float* __restrict__ Wq, const float* __restrict__ Wk,
                            const float* __restrict__ Wv)
{
    __shared__ float tile[32][33];
    const float* W = (blockIdx.z == 0) ? Wq : ((blockIdx.z == 1) ? Wk : Wv);
    __nv_bfloat16* WTh = g_WTh[blockIdx.z];
    __nv_bfloat16* WTl = g_WTl[blockIdx.z];
    int x = blockIdx.x * 32 + threadIdx.x;
    int y = blockIdx.y * 32 + threadIdx.y;
#pragma unroll
    for (int j = 0; j < 32; j += 8)
        tile[threadIdx.y + j][threadIdx.x] = W[(y + j) * DMODEL + x];
    __syncthreads();
    x = blockIdx.y * 32 + threadIdx.x;
    y = blockIdx.x * 32 + threadIdx.y;
#pragma unroll
    for (int j = 0; j < 32; j += 8) {
        float v = tile[threadIdx.x][threadIdx.y + j];
        __nv_bfloat16 h, l;
        split_bf16(v, h, l);
        WTh[(y + j) * DMODEL + x] = h;
        WTl[(y + j) * DMODEL + x] = l;
    }
}

// ---------------------------------------------------------------------------
// Projection GEMM, pure-bf16 hot loop with cp.async 2-stage pipeline:
//   C[8192,768] = (Ah+Al)[8192,768] @ (WTh+WTl)[768,768]^T + bias  (3-term)
// CTA tile 128x128, K-chunk 16, 48KB static smem, 8 warps = 2x4.
// ---------------------------------------------------------------------------
#define APAD 24

__global__ __launch_bounds__(256, 2)
void proj_mma(const __nv_bfloat16* __restrict__ Ahg,
              const __nv_bfloat16* __restrict__ Alg,
              const float* __restrict__ bias, int sel)
{
    // [stage][array(Ah,Al,Bh,Bl)][row][APAD]
    __shared__ __nv_bfloat16 S[2][4][128][APAD];

    float* __restrict__ C = (sel == 0) ? g_Q : ((sel == 1) ? g_K : g_V);
    const __nv_bfloat16* __restrict__ Bhg = g_WTh[sel];
    const __nv_bfloat16* __restrict__ Blg = g_WTl[sel];

    const int tid = threadIdx.x;
    const int lane = tid & 31;
    const int wid = tid >> 5;
    const int warp_m = wid >> 2;
    const int warp_n = wid & 3;
    const int bm = blockIdx.y * 128;
    const int bn = blockIdx.x * 128;

    // loader mapping: thread -> (row, half); covers all 4 arrays
    const int lr = tid >> 1;
    const int lh = (tid & 1) * 8;
    const uint32_t sbase = smem_u32(S);

    // fragment mapping
    const int fr = lane >> 2;
    const int fk = (lane & 3) * 2;

    float acc[4][4][4];
#pragma unroll
    for (int i = 0; i < 4; i++)
#pragma unroll
        for (int j = 0; j < 4; j++)
#pragma unroll
            for (int r = 0; r < 4; r++) acc[i][j][r] = 0.f;

    const size_t arow = (size_t)(bm + lr) * DMODEL + lh;
    const size_t brow = (size_t)(bn + lr) * DMODEL + lh;
    const uint32_t dAh = sbase + (uint32_t)(0 * 3072 + lr * APAD + lh) * 2;
    const uint32_t dAl = sbase + (uint32_t)(1 * 3072 + lr * APAD + lh) * 2;
    const uint32_t dBh = sbase + (uint32_t)(2 * 3072 + lr * APAD + lh) * 2;
    const uint32_t dBl = sbase + (uint32_t)(3 * 3072 + lr * APAD + lh) * 2;
    const uint32_t stg = 4 * 3072 * 2;   // bytes per stage

    const int NCH = DMODEL / 16;   // 48

    // prologue: issue chunks 0 and 1
#pragma unroll
    for (int c = 0; c < 2; c++) {
        uint32_t so = c * stg;
        int k0 = c * 16;
        CP_ASYNC16(dAh + so, Ahg + arow + k0);
        CP_ASYNC16(dAl + so, Alg + arow + k0);
        CP_ASYNC16(dBh + so, Bhg + brow + k0);
        CP_ASYNC16(dBl + so, Blg + brow + k0);
        CP_COMMIT();
    }

    for (int c = 0; c < NCH; c++) {
        const int buf = c & 1;
        CP_WAIT1();
        __syncthreads();

        const __nv_bfloat16 (*Ah)[APAD] = S[buf][0];
        const __nv_bfloat16 (*Al)[APAD] = S[buf][1];
        const __nv_bfloat16 (*Bh)[APAD] = S[buf][2];
        const __nv_bfloat16 (*Bl)[APAD] = S[buf][3];

        uint32_t fah[4][4], fal[4][4], fbh[4][2], fbl[4][2];
#pragma unroll
        for (int mt = 0; mt < 4; mt++) {
            int r = warp_m * 64 + mt * 16 + fr;
            fah[mt][0] = *(const uint32_t*)&Ah[r][fk];
            fah[mt][1] = *(const uint32_t*)&Ah[r + 8][fk];
            fah[mt][2] = *(const uint32_t*)&Ah[r][fk + 8];
            fah[mt][3] = *(const uint32_t*)&Ah[r + 8][fk + 8];
            fal[mt][0] = *(const uint32_t*)&Al[r][fk];
            fal[mt][1] = *(const uint32_t*)&Al[r + 8][fk];
            fal[mt][2] = *(const uint32_t*)&Al[r][fk + 8];
            fal[mt][3] = *(const uint32_t*)&Al[r + 8][fk + 8];
        }
#pragma unroll
        for (int nt = 0; nt < 4; nt++) {
            int n = warp_n * 32 + nt * 8 + fr;
            fbh[nt][0] = *(const uint32_t*)&Bh[n][fk];
            fbh[nt][1] = *(const uint32_t*)&Bh[n][fk + 8];
            fbl[nt][0] = *(const uint32_t*)&Bl[n][fk];
            fbl[nt][1] = *(const uint32_t*)&Bl[n][fk + 8];
        }

#pragma unroll
        for (int mt = 0; mt < 4; mt++)
#pragma unroll
            for (int nt = 0; nt < 4; nt++) {
                mma16816(acc[mt][nt], fah[mt], fbh[nt]);
                mma16816(acc[mt][nt], fah[mt], fbl[nt]);
                mma16816(acc[mt][nt], fal[mt], fbh[nt]);
            }

        __syncthreads();   // all warps done reading buf before refill

        if (c + 2 < NCH) {
            uint32_t so = buf * stg;
            int k0 = (c + 2) * 16;
            CP_ASYNC16(dAh + so, Ahg + arow + k0);
            CP_ASYNC16(dAl + so, Alg + arow + k0);
            CP_ASYNC16(dBh + so, Bhg + brow + k0);
            CP_ASYNC16(dBl + so, Blg + brow + k0);
        }
        CP_COMMIT();   // always commit to keep group counting uniform
    }

    // epilogue
#pragma unroll
    for (int mt = 0; mt < 4; mt++) {
#pragma unroll
        for (int nt = 0; nt < 4; nt++) {
            int rg = bm + warp_m * 64 + mt * 16 + fr;
            int cg = bn + warp_n * 32 + nt * 8 + fk;
            float b0 = __ldg(bias + cg), b1 = __ldg(bias + cg + 1);
            float2 o0 = { acc[mt][nt][0] + b0, acc[mt][nt][1] + b1 };
            float2 o1 = { acc[mt][nt][2] + b0, acc[mt][nt][3] + b1 };
            *(float2*)&C[(size_t)rg * DMODEL + cg] = o0;
            *(float2*)&C[(size_t)(rg + 8) * DMODEL + cg] = o1;
        }
    }
}

// ---------------------------------------------------------------------------
// Fused attention (unchanged): block = (b, h, 64-row q-tile)
// ---------------------------------------------------------------------------
__global__ __launch_bounds__(256)
void attn_kernel(float* __restrict__ Out)
{
    __shared__ float Qt[64 * 64];
    __shared__ float KP[64 * 64];
    __shared__ float Vs[64 * 64];

    int tid = threadIdx.x;
    int b  = blockIdx.z;
    int h  = blockIdx.y;
    int q0 = blockIdx.x * 64;

    int tc = tid & 15;
    int tr = tid >> 4;

    {
        int row = tid >> 2;
        int c0  = (tid & 3) * 16;
        const float* src = g_Q + ((long)b * SQL + q0 + row) * DMODEL + h * HD_ + c0;
#pragma unroll
        for (int u = 0; u < 4; u++) {
            float4 v = *(const float4*)(src + u * 4);
            Qt[(c0 + u * 4 + 0) * 64 + row] = v.x * 0.125f;
            Qt[(c0 + u * 4 + 1) * 64 + row] = v.y * 0.125f;
            Qt[(c0 + u * 4 + 2) * 64 + row] = v.z * 0.125f;
            Qt[(c0 + u * 4 + 3) * 64 + row] = v.w * 0.125f;
        }
    }

    float m[4], l[4], o[4][4];
#pragma unroll
    for (int i = 0; i < 4; i++) {
        m[i] = -1e30f; l[i] = 0.f;
#pragma unroll
        for (int j = 0; j < 4; j++) o[i][j] = 0.f;
    }

    for (int t = 0; t < 8; t++) {
        int k0 = t * 64;
        {
            int row = tid >> 2;
            int c0  = (tid & 3) * 16;
            const float* ksrc = g_K + ((long)b * SKL + k0 + row) * DMODEL + h * HD_ + c0;
            const float* vsrc = g_V + ((long)b * SKL + k0 + row) * DMODEL + h * HD_ + c0;
#pragma unroll
            for (int u = 0; u < 4; u++) {
                float4 kv = *(const float4*)(ksrc + u * 4);
                KP[(c0 + u * 4 + 0) * 64 + row] = kv.x;
                KP[(c0 + u * 4 + 1) * 64 + row] = kv.y;
                KP[(c0 + u * 4 + 2) * 64 + row] = kv.z;
                KP[(c0 + u * 4 + 3) * 64 + row] = kv.w;
                *(float4*)&Vs[row * 64 + c0 + u * 4] = *(const float4*)(vsrc + u * 4);
            }
        }
        __syncthreads();

        float acc[4][4];
#pragma unroll
        for (int i = 0; i < 4; i++)
#pragma unroll
            for (int j = 0; j < 4; j++) acc[i][j] = 0.f;

#pragma unroll 8
        for (int d = 0; d < 64; d++) {
            float4 q4 = *(const float4*)&Qt[d * 64 + tr * 4];
            float4 k4 = *(const float4*)&KP[d * 64 + tc * 4];
            float qa[4] = { q4.x, q4.y, q4.z, q4.w };
            float ka[4] = { k4.x, k4.y, k4.z, k4.w };
#pragma unroll
            for (int i = 0; i < 4; i++)
#pragma unroll
                for (int j = 0; j < 4; j++)
                    acc[i][j] = fmaf(qa[i], ka[j], acc[i][j]);
        }

        float mt[4];
#pragma unroll
        for (int i = 0; i < 4; i++) {
            mt[i] = acc[i][0];
#pragma unroll
            for (int j = 1; j < 4; j++) mt[i] = fmaxf(mt[i], acc[i][j]);
        }
#pragma unroll
        for (int mask = 1; mask <= 8; mask <<= 1)
#pragma unroll
            for (int i = 0; i < 4; i++)
                mt[i] = fmaxf(mt[i], __shfl_xor_sync(0xffffffffu, mt[i], mask));

        float corr[4], ls[4];
#pragma unroll
        for (int i = 0; i < 4; i++) {
            float mn = fmaxf(m[i], mt[i]);
            corr[i] = __expf(m[i] - mn);
            m[i] = mn;
            float s = 0.f;
#pragma unroll
            for (int j = 0; j < 4; j++) {
                acc[i][j] = __expf(acc[i][j] - mn);
                s += acc[i][j];
            }
            ls[i] = s;
        }
#pragma unroll
        for (int mask = 1; mask <= 8; mask <<= 1)
#pragma unroll
            for (int i = 0; i < 4; i++)
                ls[i] += __shfl_xor_sync(0xffffffffu, ls[i], mask);
#pragma unroll
        for (int i = 0; i < 4; i++) {
            l[i] = l[i] * corr[i] + ls[i];
#pragma unroll
            for (int j = 0; j < 4; j++) o[i][j] *= corr[i];
        }

        __syncthreads();

#pragma unroll
        for (int j = 0; j < 4; j++)
#pragma unroll
            for (int i = 0; i < 4; i++)
                KP[(tc * 4 + j) * 64 + tr * 4 + i] = acc[i][j];
        __syncwarp();

#pragma unroll 4
        for (int c = 0; c < 64; c++) {
            float p0 = KP[c * 64 + tr * 4 + 0];
            float p1 = KP[c * 64 + tr * 4 + 1];
            float p2 = KP[c * 64 + tr * 4 + 2];
            float p3 = KP[c * 64 + tr * 4 + 3];
            float4 v4 = *(const float4*)&Vs[c * 64 + tc * 4];
            o[0][0] = fmaf(p0, v4.x, o[0][0]); o[0][1] = fmaf(p0, v4.y, o[0][1]);
            o[0][2] = fmaf(p0, v4.z, o[0][2]); o[0][3] = fmaf(p0, v4.w, o[0][3]);
            o[1][0] = fmaf(p1, v4.x, o[1][0]); o[1][1] = fmaf(p1, v4.y, o[1][1]);
            o[1][2] = fmaf(p1, v4.z, o[1][2]); o[1][3] = fmaf(p1, v4.w, o[1][3]);
            o[2][0] = fmaf(p2, v4.x, o[2][0]); o[2][1] = fmaf(p2, v4.y, o[2][1]);
            o[2][2] = fmaf(p2, v4.z, o[2][2]); o[2][3] = fmaf(p2, v4.w, o[2][3]);
            o[3][0] = fmaf(p3, v4.x, o[3][0]); o[3][1] = fmaf(p3, v4.y, o[3][1]);
            o[3][2] = fmaf(p3, v4.z, o[3][2]); o[3][3] = fmaf(p3, v4.w, o[3][3]);
        }
        __syncthreads();
    }

#pragma unroll
    for (int i = 0; i < 4; i++) {
        float inv = 1.f / l[i];
        float4 ov;
        ov.x = o[i][0] * inv;
        ov.y = o[i][1] * inv;
        ov.z = o[i][2] * inv;
        ov.w = o[i][3] * inv;
        *(float4*)&Out[((long)b * SQL + q0 + tr * 4 + i) * DMODEL + h * HD_ + tc * 4] = ov;
    }
}

// ---------------------------------------------------------------------------
extern "C" void kernel_launch(void* const* d_in, const int* in_sizes, int n_in,
                              void* d_out, int out_size)
{
    const float* hidden  = (const float*)d_in[0];
    const float* context = (const float*)d_in[1];
    const float* Wq = (const float*)d_in[2];
    const float* bq = (const float*)d_in[3];
    const float* Wk = (const float*)d_in[4];
    const float* bk = (const float*)d_in[5];
    const float* Wv = (const float*)d_in[6];
    const float* bv = (const float*)d_in[7];
    float* out = (float*)d_out;

    static __nv_bfloat16 *hh = nullptr, *hl = nullptr, *ch = nullptr, *cl = nullptr;
    if (!hh) {
        cudaGetSymbolAddress((void**)&hh, g_Hh);
        cudaGetSymbolAddress((void**)&hl, g_Hl);
        cudaGetSymbolAddress((void**)&ch, g_Ch);
        cudaGetSymbolAddress((void**)&cl, g_Cl);
    }

    const int NEL = B_ * SQL * DMODEL;           // 6.29M
    split_in<<<NEL / 4 / 256, 256>>>(hidden,  hh, hl);
    split_in<<<NEL / 4 / 256, 256>>>(context, ch, cl);

    dim3 tgrid(DMODEL / 32, DMODEL / 32, 3);
    transpose_w<<<tgrid, dim3(32, 8)>>>(Wq, Wk, Wv);

    dim3 pgrid(DMODEL / 128, (B_ * SQL) / 128);   // (6, 64)
    proj_mma<<<pgrid, 256>>>(hh, hl, bq, 0);
    proj_mma<<<pgrid, 256>>>(ch, cl, bk, 1);
    proj_mma<<<pgrid, 256>>>(ch, cl, bv, 2);

    dim3 agrid(SQL / 64, NH, B_);                 // (8, 12, 16)
    attn_kernel<<<agrid, 256>>>(out);
}

// round 5
// speedup vs baseline: 1.9122x; 1.3085x over previous
#include <cuda_runtime.h>
#include <cuda_bf16.h>
#include <cstdint>

#define B_      16
#define SQL     512
#define SKL     512
#define DMODEL  768
#define NH      12
#define HD_     64

// ---------------------------------------------------------------------------
// Static device scratch (allocation-free, graph-safe)
// ---------------------------------------------------------------------------
// pre-split bf16 inputs (hi/lo) and transposed+split weights
__device__ __nv_bfloat16 g_Hh[B_ * SQL * DMODEL];   // hidden hi
__device__ __nv_bfloat16 g_Hl[B_ * SQL * DMODEL];   // hidden lo
__device__ __nv_bfloat16 g_Ch[B_ * SKL * DMODEL];   // context hi
__device__ __nv_bfloat16 g_Cl[B_ * SKL * DMODEL];   // context lo
__device__ __nv_bfloat16 g_WTh[3][DMODEL * DMODEL]; // W^T hi  [n][k]
__device__ __nv_bfloat16 g_WTl[3][DMODEL * DMODEL]; // W^T lo  [n][k]
// projected Q/K/V as bf16 hi/lo (Q pre-scaled by 0.125)
__device__ __nv_bfloat16 g_Oh[3][B_ * SQL * DMODEL];
__device__ __nv_bfloat16 g_Ol[3][B_ * SQL * DMODEL];

// ---------------------------------------------------------------------------
__device__ __forceinline__ uint32_t smem_u32(const void* p) {
    uint32_t a;
    asm("{ .reg .u64 t; cvta.to.shared.u64 t, %1; cvt.u32.u64 %0, t; }" : "=r"(a) : "l"(p));
    return a;
}
#define CP_ASYNC16(dst, src) \
    asm volatile("cp.async.cg.shared.global [%0], [%1], 16;" :: "r"(dst), "l"(src))
#define CP_COMMIT() asm volatile("cp.async.commit_group;" ::: "memory")
#define CP_WAIT1()  asm volatile("cp.async.wait_group 1;" ::: "memory")
#define CP_WAIT0()  asm volatile("cp.async.wait_group 0;" ::: "memory")

__device__ __forceinline__ void mma16816(float* d, const uint32_t* a, const uint32_t* b)
{
    asm volatile(
        "mma.sync.aligned.m16n8k16.row.col.f32.bf16.bf16.f32 "
        "{%0,%1,%2,%3}, {%4,%5,%6,%7}, {%8,%9}, {%0,%1,%2,%3};"
        : "+f"(d[0]), "+f"(d[1]), "+f"(d[2]), "+f"(d[3])
        : "r"(a[0]), "r"(a[1]), "r"(a[2]), "r"(a[3]), "r"(b[0]), "r"(b[1]));
}

__device__ __forceinline__ void split_bf16(float x, __nv_bfloat16& hi, __nv_bfloat16& lo)
{
    hi = __float2bfloat16_rn(x);
    lo = __float2bfloat16_rn(x - __bfloat162float(hi));
}
__device__ __forceinline__ uint32_t pack_bf2(__nv_bfloat16 a, __nv_bfloat16 b)
{
    __nv_bfloat162 t; t.x = a; t.y = b;
    return *(uint32_t*)&t;
}

// ---------------------------------------------------------------------------
// Pre-split input: X fp32 -> Xh + Xl bf16
// ---------------------------------------------------------------------------
__global__ void split_in(const float* __restrict__ X,
                         __nv_bfloat16* __restrict__ Xh,
                         __nv_bfloat16* __restrict__ Xl)
{
    int i = (blockIdx.x * blockDim.x + threadIdx.x) * 4;
    float4 v = *(const float4*)(X + i);
    __nv_bfloat162 h0, h1, l0, l1;
    split_bf16(v.x, h0.x, l0.x); split_bf16(v.y, h0.y, l0.y);
    split_bf16(v.z, h1.x, l1.x); split_bf16(v.w, h1.y, l1.y);
    *(__nv_bfloat162*)(Xh + i)     = h0;
    *(__nv_bfloat162*)(Xh + i + 2) = h1;
    *(__nv_bfloat162*)(Xl + i)     = l0;
    *(__nv_bfloat162*)(Xl + i + 2) = l1;
}

// ---------------------------------------------------------------------------
// Transpose + split weights
// ---------------------------------------------------------------------------
__global__ void transpose_w(const float* __restrict__ Wq, const float* __restrict__ Wk,
                            const float* __restrict__ Wv)
{
    __shared__ float tile[32][33];
    const float* W = (blockIdx.z == 0) ? Wq : ((blockIdx.z == 1) ? Wk : Wv);
    __nv_bfloat16* WTh = g_WTh[blockIdx.z];
    __nv_bfloat16* WTl = g_WTl[blockIdx.z];
    int x = blockIdx.x * 32 + threadIdx.x;
    int y = blockIdx.y * 32 + threadIdx.y;
#pragma unroll
    for (int j = 0; j < 32; j += 8)
        tile[threadIdx.y + j][threadIdx.x] = W[(y + j) * DMODEL + x];
    __syncthreads();
    x = blockIdx.y * 32 + threadIdx.x;
    y = blockIdx.x * 32 + threadIdx.y;
#pragma unroll
    for (int j = 0; j < 32; j += 8) {
        float v = tile[threadIdx.x][threadIdx.y + j];
        __nv_bfloat16 h, l;
        split_bf16(v, h, l);
        WTh[(y + j) * DMODEL + x] = h;
        WTl[(y + j) * DMODEL + x] = l;
    }
}

// ---------------------------------------------------------------------------
// Projection GEMM (bf16 hot loop, cp.async 2-stage).
// Epilogue writes bf16 hi/lo (Q scaled by 0.125).
// ---------------------------------------------------------------------------
#define APAD 24

__global__ __launch_bounds__(256, 2)
void proj_mma(const __nv_bfloat16* __restrict__ Ahg,
              const __nv_bfloat16* __restrict__ Alg,
              const float* __restrict__ bias, int sel)
{
    __shared__ __nv_bfloat16 S[2][4][128][APAD];

    __nv_bfloat16* __restrict__ Oh = g_Oh[sel];
    __nv_bfloat16* __restrict__ Ol = g_Ol[sel];
    const __nv_bfloat16* __restrict__ Bhg = g_WTh[sel];
    const __nv_bfloat16* __restrict__ Blg = g_WTl[sel];
    const float scale = (sel == 0) ? 0.125f : 1.0f;

    const int tid = threadIdx.x;
    const int lane = tid & 31;
    const int wid = tid >> 5;
    const int warp_m = wid >> 2;
    const int warp_n = wid & 3;
    const int bm = blockIdx.y * 128;
    const int bn = blockIdx.x * 128;

    const int lr = tid >> 1;
    const int lh = (tid & 1) * 8;
    const uint32_t sbase = smem_u32(S);

    const int fr = lane >> 2;
    const int fk = (lane & 3) * 2;

    float acc[4][4][4];
#pragma unroll
    for (int i = 0; i < 4; i++)
#pragma unroll
        for (int j = 0; j < 4; j++)
#pragma unroll
            for (int r = 0; r < 4; r++) acc[i][j][r] = 0.f;

    const size_t arow = (size_t)(bm + lr) * DMODEL + lh;
    const size_t brow = (size_t)(bn + lr) * DMODEL + lh;
    const uint32_t dAh = sbase + (uint32_t)(0 * 3072 + lr * APAD + lh) * 2;
    const uint32_t dAl = sbase + (uint32_t)(1 * 3072 + lr * APAD + lh) * 2;
    const uint32_t dBh = sbase + (uint32_t)(2 * 3072 + lr * APAD + lh) * 2;
    const uint32_t dBl = sbase + (uint32_t)(3 * 3072 + lr * APAD + lh) * 2;
    const uint32_t stg = 4 * 3072 * 2;

    const int NCH = DMODEL / 16;

#pragma unroll
    for (int c = 0; c < 2; c++) {
        uint32_t so = c * stg;
        int k0 = c * 16;
        CP_ASYNC16(dAh + so, Ahg + arow + k0);
        CP_ASYNC16(dAl + so, Alg + arow + k0);
        CP_ASYNC16(dBh + so, Bhg + brow + k0);
        CP_ASYNC16(dBl + so, Blg + brow + k0);
        CP_COMMIT();
    }

    for (int c = 0; c < NCH; c++) {
        const int buf = c & 1;
        CP_WAIT1();
        __syncthreads();

        const __nv_bfloat16 (*Ah)[APAD] = S[buf][0];
        const __nv_bfloat16 (*Al)[APAD] = S[buf][1];
        const __nv_bfloat16 (*Bh)[APAD] = S[buf][2];
        const __nv_bfloat16 (*Bl)[APAD] = S[buf][3];

        uint32_t fah[4][4], fal[4][4], fbh[4][2], fbl[4][2];
#pragma unroll
        for (int mt = 0; mt < 4; mt++) {
            int r = warp_m * 64 + mt * 16 + fr;
            fah[mt][0] = *(const uint32_t*)&Ah[r][fk];
            fah[mt][1] = *(const uint32_t*)&Ah[r + 8][fk];
            fah[mt][2] = *(const uint32_t*)&Ah[r][fk + 8];
            fah[mt][3] = *(const uint32_t*)&Ah[r + 8][fk + 8];
            fal[mt][0] = *(const uint32_t*)&Al[r][fk];
            fal[mt][1] = *(const uint32_t*)&Al[r + 8][fk];
            fal[mt][2] = *(const uint32_t*)&Al[r][fk + 8];
            fal[mt][3] = *(const uint32_t*)&Al[r + 8][fk + 8];
        }
#pragma unroll
        for (int nt = 0; nt < 4; nt++) {
            int n = warp_n * 32 + nt * 8 + fr;
            fbh[nt][0] = *(const uint32_t*)&Bh[n][fk];
            fbh[nt][1] = *(const uint32_t*)&Bh[n][fk + 8];
            fbl[nt][0] = *(const uint32_t*)&Bl[n][fk];
            fbl[nt][1] = *(const uint32_t*)&Bl[n][fk + 8];
        }

#pragma unroll
        for (int mt = 0; mt < 4; mt++)
#pragma unroll
            for (int nt = 0; nt < 4; nt++) {
                mma16816(acc[mt][nt], fah[mt], fbh[nt]);
                mma16816(acc[mt][nt], fah[mt], fbl[nt]);
                mma16816(acc[mt][nt], fal[mt], fbh[nt]);
            }

        __syncthreads();

        if (c + 2 < NCH) {
            uint32_t so = buf * stg;
            int k0 = (c + 2) * 16;
            CP_ASYNC16(dAh + so, Ahg + arow + k0);
            CP_ASYNC16(dAl + so, Alg + arow + k0);
            CP_ASYNC16(dBh + so, Bhg + brow + k0);
            CP_ASYNC16(dBl + so, Blg + brow + k0);
        }
        CP_COMMIT();
    }

    // epilogue: bias, scale, split to bf16 hi/lo
#pragma unroll
    for (int mt = 0; mt < 4; mt++) {
#pragma unroll
        for (int nt = 0; nt < 4; nt++) {
            int rg = bm + warp_m * 64 + mt * 16 + fr;
            int cg = bn + warp_n * 32 + nt * 8 + fk;
            float b0 = __ldg(bias + cg), b1 = __ldg(bias + cg + 1);
            float v00 = (acc[mt][nt][0] + b0) * scale;
            float v01 = (acc[mt][nt][1] + b1) * scale;
            float v10 = (acc[mt][nt][2] + b0) * scale;
            float v11 = (acc[mt][nt][3] + b1) * scale;
            __nv_bfloat16 h, l;
            __nv_bfloat162 hh, ll;
            split_bf16(v00, h, l); hh.x = h; ll.x = l;
            split_bf16(v01, h, l); hh.y = h; ll.y = l;
            *(__nv_bfloat162*)&Oh[(size_t)rg * DMODEL + cg] = hh;
            *(__nv_bfloat162*)&Ol[(size_t)rg * DMODEL + cg] = ll;
            split_bf16(v10, h, l); hh.x = h; ll.x = l;
            split_bf16(v11, h, l); hh.y = h; ll.y = l;
            *(__nv_bfloat162*)&Oh[(size_t)(rg + 8) * DMODEL + cg] = hh;
            *(__nv_bfloat162*)&Ol[(size_t)(rg + 8) * DMODEL + cg] = ll;
        }
    }
}

// ---------------------------------------------------------------------------
// HMMA flash attention: block = (b, h, 64 q-rows), 4 warps x 16 q-rows.
// S = QK^T (3-term split), online softmax on accumulators, P-fragments built
// in registers, O += P V (3-term split). V transposed into smem at load.
// ---------------------------------------------------------------------------
#define VP 88   // smem row stride (bf16): 176B, 16B-aligned, conflict-free frags

__global__ __launch_bounds__(128)
void attn_mma(float* __restrict__ Out)
{
    __shared__ __nv_bfloat16 Kh[64][VP];
    __shared__ __nv_bfloat16 Kl[64][VP];
    __shared__ __nv_bfloat16 Vth[64][VP];
    __shared__ __nv_bfloat16 Vtl[64][VP];

    const int tid = threadIdx.x;
    const int lane = tid & 31;
    const int wid = tid >> 5;            // 0..3 -> q rows [wid*16, wid*16+16)
    const int b  = blockIdx.z;
    const int h  = blockIdx.y;
    const int q0 = blockIdx.x * 64;

    const int fr = lane >> 2;
    const int fk = (lane & 3) * 2;

    const __nv_bfloat16* __restrict__ Qh = g_Oh[0];
    const __nv_bfloat16* __restrict__ Ql = g_Ol[0];
    const __nv_bfloat16* __restrict__ Kgh = g_Oh[1];
    const __nv_bfloat16* __restrict__ Kgl = g_Ol[1];
    const __nv_bfloat16* __restrict__ Vgh = g_Oh[2];
    const __nv_bfloat16* __restrict__ Vgl = g_Ol[2];

    // loader mapping (cp.async): row = tid>>1 (0..63), half = tid&1 -> 4x16B
    const int lr = tid >> 1;
    const int lh = (tid & 1) * 32;       // bf16 offset within row
    const uint32_t aKh = smem_u32(&Kh[lr][lh]);
    const uint32_t aKl = smem_u32(&Kl[lr][lh]);

    // ---- stage Q through Kh/Kl smem, extract fragments to registers ----
    {
        const __nv_bfloat16* qsrc_h = Qh + ((size_t)(b * SQL + q0 + lr)) * DMODEL + h * HD_ + lh;
        const __nv_bfloat16* qsrc_l = Ql + ((size_t)(b * SQL + q0 + lr)) * DMODEL + h * HD_ + lh;
#pragma unroll
        for (int j = 0; j < 4; j++) {
            CP_ASYNC16(aKh + j * 16, qsrc_h + j * 8);
            CP_ASYNC16(aKl + j * 16, qsrc_l + j * 8);
        }
        CP_COMMIT();
        CP_WAIT0();
        __syncthreads();
    }
    uint32_t qfh[4][4], qfl[4][4];
#pragma unroll
    for (int kc = 0; kc < 4; kc++) {
        int r = wid * 16 + fr;
        qfh[kc][0] = *(const uint32_t*)&Kh[r][kc * 16 + fk];
        qfh[kc][1] = *(const uint32_t*)&Kh[r + 8][kc * 16 + fk];
        qfh[kc][2] = *(const uint32_t*)&Kh[r][kc * 16 + fk + 8];
        qfh[kc][3] = *(const uint32_t*)&Kh[r + 8][kc * 16 + fk + 8];
        qfl[kc][0] = *(const uint32_t*)&Kl[r][kc * 16 + fk];
        qfl[kc][1] = *(const uint32_t*)&Kl[r + 8][kc * 16 + fk];
        qfl[kc][2] = *(const uint32_t*)&Kl[r][kc * 16 + fk + 8];
        qfl[kc][3] = *(const uint32_t*)&Kl[r + 8][kc * 16 + fk + 8];
    }
    __syncthreads();

    float m0 = -1e30f, m1 = -1e30f, l0 = 0.f, l1 = 0.f;
    float accO[8][4];
#pragma unroll
    for (int dt = 0; dt < 8; dt++)
#pragma unroll
        for (int r = 0; r < 4; r++) accO[dt][r] = 0.f;

    // V transpose mapping: c = tid>>1 (key), d pairs from (tid&1)
    const int vc = tid >> 1;
    const int vd0 = (tid & 1) * 32;

    for (int t = 0; t < 8; t++) {
        const int k0 = t * 64;
        // K tiles via cp.async (natural [key][d])
        {
            const __nv_bfloat16* kh = Kgh + ((size_t)(b * SKL + k0 + lr)) * DMODEL + h * HD_ + lh;
            const __nv_bfloat16* kl = Kgl + ((size_t)(b * SKL + k0 + lr)) * DMODEL + h * HD_ + lh;
#pragma unroll
            for (int j = 0; j < 4; j++) {
                CP_ASYNC16(aKh + j * 16, kh + j * 8);
                CP_ASYNC16(aKl + j * 16, kl + j * 8);
            }
            CP_COMMIT();
        }
        // V transpose: read [c][d] bf16x2, write Vt[d][c]
        {
            const __nv_bfloat16* vh = Vgh + ((size_t)(b * SKL + k0 + vc)) * DMODEL + h * HD_ + vd0;
            const __nv_bfloat16* vl = Vgl + ((size_t)(b * SKL + k0 + vc)) * DMODEL + h * HD_ + vd0;
#pragma unroll
            for (int p = 0; p < 16; p++) {
                __nv_bfloat162 v2 = *(const __nv_bfloat162*)(vh + p * 2);
                Vth[vd0 + p * 2][vc] = v2.x;
                Vth[vd0 + p * 2 + 1][vc] = v2.y;
                v2 = *(const __nv_bfloat162*)(vl + p * 2);
                Vtl[vd0 + p * 2][vc] = v2.x;
                Vtl[vd0 + p * 2 + 1][vc] = v2.y;
            }
        }
        CP_WAIT0();
        __syncthreads();

        // ---- S = Q K^T ----
        float accS[8][4];
#pragma unroll
        for (int nt = 0; nt < 8; nt++) {
            accS[nt][0] = accS[nt][1] = accS[nt][2] = accS[nt][3] = 0.f;
            uint32_t kbh[4][2], kbl[4][2];
#pragma unroll
            for (int kc = 0; kc < 4; kc++) {
                int n = nt * 8 + fr;
                kbh[kc][0] = *(const uint32_t*)&Kh[n][kc * 16 + fk];
                kbh[kc][1] = *(const uint32_t*)&Kh[n][kc * 16 + fk + 8];
                kbl[kc][0] = *(const uint32_t*)&Kl[n][kc * 16 + fk];
                kbl[kc][1] = *(const uint32_t*)&Kl[n][kc * 16 + fk + 8];
            }
#pragma unroll
            for (int kc = 0; kc < 4; kc++) {
                mma16816(accS[nt], qfh[kc], kbh[kc]);
                mma16816(accS[nt], qfh[kc], kbl[kc]);
                mma16816(accS[nt], qfl[kc], kbh[kc]);
            }
        }

        // ---- online softmax (rows fr and fr+8) ----
        float mt0 = -1e30f, mt1 = -1e30f;
#pragma unroll
        for (int nt = 0; nt < 8; nt++) {
            mt0 = fmaxf(mt0, fmaxf(accS[nt][0], accS[nt][1]));
            mt1 = fmaxf(mt1, fmaxf(accS[nt][2], accS[nt][3]));
        }
        mt0 = fmaxf(mt0, __shfl_xor_sync(0xffffffffu, mt0, 1));
        mt0 = fmaxf(mt0, __shfl_xor_sync(0xffffffffu, mt0, 2));
        mt1 = fmaxf(mt1, __shfl_xor_sync(0xffffffffu, mt1, 1));
        mt1 = fmaxf(mt1, __shfl_xor_sync(0xffffffffu, mt1, 2));

        float mn0 = fmaxf(m0, mt0), mn1 = fmaxf(m1, mt1);
        float c0 = __expf(m0 - mn0), c1 = __expf(m1 - mn1);
        m0 = mn0; m1 = mn1;

        float s0 = 0.f, s1 = 0.f;
#pragma unroll
        for (int nt = 0; nt < 8; nt++) {
            accS[nt][0] = __expf(accS[nt][0] - mn0);
            accS[nt][1] = __expf(accS[nt][1] - mn0);
            accS[nt][2] = __expf(accS[nt][2] - mn1);
            accS[nt][3] = __expf(accS[nt][3] - mn1);
            s0 += accS[nt][0] + accS[nt][1];
            s1 += accS[nt][2] + accS[nt][3];
        }
        s0 += __shfl_xor_sync(0xffffffffu, s0, 1);
        s0 += __shfl_xor_sync(0xffffffffu, s0, 2);
        s1 += __shfl_xor_sync(0xffffffffu, s1, 1);
        s1 += __shfl_xor_sync(0xffffffffu, s1, 2);
        l0 = l0 * c0 + s0;
        l1 = l1 * c1 + s1;
#pragma unroll
        for (int dt = 0; dt < 8; dt++) {
            accO[dt][0] *= c0; accO[dt][1] *= c0;
            accO[dt][2] *= c1; accO[dt][3] *= c1;
        }

        // ---- build P fragments in registers (hi/lo split) ----
        uint32_t pfh[4][4], pfl[4][4];
#pragma unroll
        for (int kc = 0; kc < 4; kc++) {
            __nv_bfloat16 h00, l00, h01, l01;
            split_bf16(accS[2 * kc][0], h00, l00);
            split_bf16(accS[2 * kc][1], h01, l01);
            pfh[kc][0] = pack_bf2(h00, h01);
            pfl[kc][0] = pack_bf2(l00, l01);
            split_bf16(accS[2 * kc][2], h00, l00);
            split_bf16(accS[2 * kc][3], h01, l01);
            pfh[kc][1] = pack_bf2(h00, h01);
            pfl[kc][1] = pack_bf2(l00, l01);
            split_bf16(accS[2 * kc + 1][0], h00, l00);
            split_bf16(accS[2 * kc + 1][1], h01, l01);
            pfh[kc][2] = pack_bf2(h00, h01);
            pfl[kc][2] = pack_bf2(l00, l01);
            split_bf16(accS[2 * kc + 1][2], h00, l00);
            split_bf16(accS[2 * kc + 1][3], h01, l01);
            pfh[kc][3] = pack_bf2(h00, h01);
            pfl[kc][3] = pack_bf2(l00, l01);
        }

        // ---- O += P V ----
#pragma unroll
        for (int dt = 0; dt < 8; dt++) {
            int n = dt * 8 + fr;
#pragma unroll
            for (int kc = 0; kc < 4; kc++) {
                uint32_t vbh[2], vbl[2];
                vbh[0] = *(const uint32_t*)&Vth[n][kc * 16 + fk];
                vbh[1] = *(const uint32_t*)&Vth[n][kc * 16 + fk + 8];
                vbl[0] = *(const uint32_t*)&Vtl[n][kc * 16 + fk];
                vbl[1] = *(const uint32_t*)&Vtl[n][kc * 16 + fk + 8];
                mma16816(accO[dt], pfh[kc], vbh);
                mma16816(accO[dt], pfh[kc], vbl);
                mma16816(accO[dt], pfl[kc], vbh);
            }
        }
        __syncthreads();   // all reads done before next tile overwrites smem
    }

    // ---- epilogue ----
    float inv0 = 1.f / l0, inv1 = 1.f / l1;
    int row0 = b * SQL + q0 + wid * 16 + fr;
#pragma unroll
    for (int dt = 0; dt < 8; dt++) {
        int col = h * HD_ + dt * 8 + fk;
        float2 o0 = { accO[dt][0] * inv0, accO[dt][1] * inv0 };
        float2 o1 = { accO[dt][2] * inv1, accO[dt][3] * inv1 };
        *(float2*)&Out[(size_t)row0 * DMODEL + col] = o0;
        *(float2*)&Out[(size_t)(row0 + 8) * DMODEL + col] = o1;
    }
}

// ---------------------------------------------------------------------------
extern "C" void kernel_launch(void* const* d_in, const int* in_sizes, int n_in,
                              void* d_out, int out_size)
{
    const float* hidden  = (const float*)d_in[0];
    const float* context = (const float*)d_in[1];
    const float* Wq = (const float*)d_in[2];
    const float* bq = (const float*)d_in[3];
    const float* Wk = (const float*)d_in[4];
    const float* bk = (const float*)d_in[5];
    const float* Wv = (const float*)d_in[6];
    const float* bv = (const float*)d_in[7];
    float* out = (float*)d_out;

    static __nv_bfloat16 *hh = nullptr, *hl = nullptr, *ch = nullptr, *cl = nullptr;
    if (!hh) {
        cudaGetSymbolAddress((void**)&hh, g_Hh);
        cudaGetSymbolAddress((void**)&hl, g_Hl);
        cudaGetSymbolAddress((void**)&ch, g_Ch);
        cudaGetSymbolAddress((void**)&cl, g_Cl);
    }

    const int NEL = B_ * SQL * DMODEL;
    split_in<<<NEL / 4 / 256, 256>>>(hidden,  hh, hl);
    split_in<<<NEL / 4 / 256, 256>>>(context, ch, cl);

    dim3 tgrid(DMODEL / 32, DMODEL / 32, 3);
    transpose_w<<<tgrid, dim3(32, 8)>>>(Wq, Wk, Wv);

    dim3 pgrid(DMODEL / 128, (B_ * SQL) / 128);   // (6, 64)
    proj_mma<<<pgrid, 256>>>(hh, hl, bq, 0);
    proj_mma<<<pgrid, 256>>>(ch, cl, bk, 1);
    proj_mma<<<pgrid, 256>>>(ch, cl, bv, 2);

    dim3 agrid(SQL / 64, NH, B_);                 // (8, 12, 16)
    attn_mma<<<agrid, 128>>>(out);
}

// round 6
// speedup vs baseline: 2.4396x; 1.2758x over previous
#include <cuda_runtime.h>
#include <cuda_bf16.h>
#include <cstdint>

#define B_      16
#define SQL     512
#define SKL     512
#define DMODEL  768
#define NH      12
#define HD_     64

// ---------------------------------------------------------------------------
// Static device scratch (allocation-free, graph-safe)
// ---------------------------------------------------------------------------
__device__ __nv_bfloat16 g_Hh[B_ * SQL * DMODEL];
__device__ __nv_bfloat16 g_Hl[B_ * SQL * DMODEL];
__device__ __nv_bfloat16 g_Ch[B_ * SKL * DMODEL];
__device__ __nv_bfloat16 g_Cl[B_ * SKL * DMODEL];
__device__ __nv_bfloat16 g_WTh[3][DMODEL * DMODEL];
__device__ __nv_bfloat16 g_WTl[3][DMODEL * DMODEL];
// projected Q/K/V bf16 hi/lo (Q pre-scaled by 0.125)
__device__ __nv_bfloat16 g_Oh[3][B_ * SQL * DMODEL];
__device__ __nv_bfloat16 g_Ol[3][B_ * SQL * DMODEL];

// ---------------------------------------------------------------------------
__device__ __forceinline__ uint32_t smem_u32(const void* p) {
    uint32_t a;
    asm("{ .reg .u64 t; cvta.to.shared.u64 t, %1; cvt.u32.u64 %0, t; }" : "=r"(a) : "l"(p));
    return a;
}
#define CP_ASYNC16(dst, src) \
    asm volatile("cp.async.cg.shared.global [%0], [%1], 16;" :: "r"(dst), "l"(src))
#define CP_COMMIT() asm volatile("cp.async.commit_group;" ::: "memory")
#define CP_WAIT1()  asm volatile("cp.async.wait_group 1;" ::: "memory")
#define CP_WAIT0()  asm volatile("cp.async.wait_group 0;" ::: "memory")

#define LDSM_X4(r, addr) \
    asm volatile("ldmatrix.sync.aligned.m8n8.x4.shared.b16 {%0,%1,%2,%3}, [%4];" \
        : "=r"((r)[0]), "=r"((r)[1]), "=r"((r)[2]), "=r"((r)[3]) : "r"(addr))
#define LDSM_X4_T(r, addr) \
    asm volatile("ldmatrix.sync.aligned.m8n8.x4.trans.shared.b16 {%0,%1,%2,%3}, [%4];" \
        : "=r"((r)[0]), "=r"((r)[1]), "=r"((r)[2]), "=r"((r)[3]) : "r"(addr))

__device__ __forceinline__ void mma16816(float* d, const uint32_t* a, const uint32_t* b)
{
    asm volatile(
        "mma.sync.aligned.m16n8k16.row.col.f32.bf16.bf16.f32 "
        "{%0,%1,%2,%3}, {%4,%5,%6,%7}, {%8,%9}, {%0,%1,%2,%3};"
        : "+f"(d[0]), "+f"(d[1]), "+f"(d[2]), "+f"(d[3])
        : "r"(a[0]), "r"(a[1]), "r"(a[2]), "r"(a[3]), "r"(b[0]), "r"(b[1]));
}

__device__ __forceinline__ void split_bf16(float x, __nv_bfloat16& hi, __nv_bfloat16& lo)
{
    hi = __float2bfloat16_rn(x);
    lo = __float2bfloat16_rn(x - __bfloat162float(hi));
}
__device__ __forceinline__ uint32_t pack_bf2(__nv_bfloat16 a, __nv_bfloat16 b)
{
    __nv_bfloat162 t; t.x = a; t.y = b;
    return *(uint32_t*)&t;
}

// ---------------------------------------------------------------------------
__global__ void split_in(const float* __restrict__ X,
                         __nv_bfloat16* __restrict__ Xh,
                         __nv_bfloat16* __restrict__ Xl)
{
    int i = (blockIdx.x * blockDim.x + threadIdx.x) * 4;
    float4 v = *(const float4*)(X + i);
    __nv_bfloat162 h0, h1, l0, l1;
    split_bf16(v.x, h0.x, l0.x); split_bf16(v.y, h0.y, l0.y);
    split_bf16(v.z, h1.x, l1.x); split_bf16(v.w, h1.y, l1.y);
    *(__nv_bfloat162*)(Xh + i)     = h0;
    *(__nv_bfloat162*)(Xh + i + 2) = h1;
    *(__nv_bfloat162*)(Xl + i)     = l0;
    *(__nv_bfloat162*)(Xl + i + 2) = l1;
}

__global__ void transpose_w(const float* __restrict__ Wq, const float* __restrict__ Wk,
                            const float* __restrict__ Wv)
{
    __shared__ float tile[32][33];
    const float* W = (blockIdx.z == 0) ? Wq : ((blockIdx.z == 1) ? Wk : Wv);
    __nv_bfloat16* WTh = g_WTh[blockIdx.z];
    __nv_bfloat16* WTl = g_WTl[blockIdx.z];
    int x = blockIdx.x * 32 + threadIdx.x;
    int y = blockIdx.y * 32 + threadIdx.y;
#pragma unroll
    for (int j = 0; j < 32; j += 8)
        tile[threadIdx.y + j][threadIdx.x] = W[(y + j) * DMODEL + x];
    __syncthreads();
    x = blockIdx.y * 32 + threadIdx.x;
    y = blockIdx.x * 32 + threadIdx.y;
#pragma unroll
    for (int j = 0; j < 32; j += 8) {
        float v = tile[threadIdx.x][threadIdx.y + j];
        __nv_bfloat16 h, l;
        split_bf16(v, h, l);
        WTh[(y + j) * DMODEL + x] = h;
        WTl[(y + j) * DMODEL + x] = l;
    }
}

// ---------------------------------------------------------------------------
// Projection GEMM: 3-stage cp.async pipeline, ldmatrix fragments,
// ONE __syncthreads per K-chunk. Dynamic smem 72KB, 2 CTAs/SM.
// ---------------------------------------------------------------------------
#define APAD 24
#define ARR_B   (128 * APAD * 2)          // 6144 bytes per array
#define STAGE_B (4 * ARR_B)               // 24576 bytes per stage
#define PROJ_SMEM (3 * STAGE_B)           // 73728 bytes

__global__ __launch_bounds__(256, 2)
void proj_mma(const __nv_bfloat16* __restrict__ Ahg,
              const __nv_bfloat16* __restrict__ Alg,
              const float* __restrict__ bias, int sel)
{
    extern __shared__ __align__(16) __nv_bfloat16 PS[];
    const uint32_t sbase = smem_u32(PS);

    __nv_bfloat16* __restrict__ Oh = g_Oh[sel];
    __nv_bfloat16* __restrict__ Ol = g_Ol[sel];
    const __nv_bfloat16* __restrict__ Bhg = g_WTh[sel];
    const __nv_bfloat16* __restrict__ Blg = g_WTl[sel];
    const float scale = (sel == 0) ? 0.125f : 1.0f;

    const int tid = threadIdx.x;
    const int lane = tid & 31;
    const int wid = tid >> 5;
    const int warp_m = wid >> 2;
    const int warp_n = wid & 3;
    const int bm = blockIdx.y * 128;
    const int bn = blockIdx.x * 128;

    // loader: 2 threads/row, 16B each
    const int lr = tid >> 1;
    const int lh = (tid & 1) * 8;
    const size_t arow = (size_t)(bm + lr) * DMODEL + lh;
    const size_t brow = (size_t)(bn + lr) * DMODEL + lh;
    const uint32_t ldst = (uint32_t)(lr * APAD + lh) * 2;   // within-array byte off

    // ldmatrix lane addressing
    const uint32_t aoffA = ((warp_m * 64 + (lane & 15)) * APAD + (lane >> 4) * 8) * 2;
    const uint32_t aoffB = ((warp_n * 32 + ((lane >> 4) << 3) + (lane & 7)) * APAD
                            + ((lane >> 3) & 1) * 8) * 2;

    const int fr = lane >> 2;
    const int fk = (lane & 3) * 2;

    float acc[4][4][4];
#pragma unroll
    for (int i = 0; i < 4; i++)
#pragma unroll
        for (int j = 0; j < 4; j++)
#pragma unroll
            for (int r = 0; r < 4; r++) acc[i][j][r] = 0.f;

    const int NCH = DMODEL / 16;   // 48

    // prologue: chunks 0,1 -> stages 0,1
#pragma unroll
    for (int c = 0; c < 2; c++) {
        uint32_t so = c * STAGE_B;
        int k0 = c * 16;
        CP_ASYNC16(sbase + so + 0 * ARR_B + ldst, Ahg + arow + k0);
        CP_ASYNC16(sbase + so + 1 * ARR_B + ldst, Alg + arow + k0);
        CP_ASYNC16(sbase + so + 2 * ARR_B + ldst, Bhg + brow + k0);
        CP_ASYNC16(sbase + so + 3 * ARR_B + ldst, Blg + brow + k0);
        CP_COMMIT();
    }

    int stage = 0;
    for (int c = 0; c < NCH; c++) {
        const uint32_t so = stage * STAGE_B;
        CP_WAIT1();
        __syncthreads();

        uint32_t fah[4][4], fal[4][4], fbh4[2][4], fbl4[2][4];
#pragma unroll
        for (int mt = 0; mt < 4; mt++) {
            LDSM_X4(fah[mt], sbase + so + 0 * ARR_B + aoffA + mt * 768);
            LDSM_X4(fal[mt], sbase + so + 1 * ARR_B + aoffA + mt * 768);
        }
#pragma unroll
        for (int pr = 0; pr < 2; pr++) {
            LDSM_X4(fbh4[pr], sbase + so + 2 * ARR_B + aoffB + pr * 768);
            LDSM_X4(fbl4[pr], sbase + so + 3 * ARR_B + aoffB + pr * 768);
        }

#pragma unroll
        for (int mt = 0; mt < 4; mt++)
#pragma unroll
            for (int nt = 0; nt < 4; nt++) {
                const uint32_t* bh = &fbh4[nt >> 1][(nt & 1) * 2];
                const uint32_t* bl = &fbl4[nt >> 1][(nt & 1) * 2];
                mma16816(acc[mt][nt], fah[mt], bh);
                mma16816(acc[mt][nt], fah[mt], bl);
                mma16816(acc[mt][nt], fal[mt], bh);
            }

        // refill stage (c+2)%3 (its previous readers finished before the sync)
        if (c + 2 < NCH) {
            int s2 = stage + 2; if (s2 >= 3) s2 -= 3;
            uint32_t so2 = s2 * STAGE_B;
            int k0 = (c + 2) * 16;
            CP_ASYNC16(sbase + so2 + 0 * ARR_B + ldst, Ahg + arow + k0);
            CP_ASYNC16(sbase + so2 + 1 * ARR_B + ldst, Alg + arow + k0);
            CP_ASYNC16(sbase + so2 + 2 * ARR_B + ldst, Bhg + brow + k0);
            CP_ASYNC16(sbase + so2 + 3 * ARR_B + ldst, Blg + brow + k0);
        }
        CP_COMMIT();
        if (++stage == 3) stage = 0;
    }

    // epilogue: bias, scale, split -> bf16 hi/lo
#pragma unroll
    for (int mt = 0; mt < 4; mt++) {
#pragma unroll
        for (int nt = 0; nt < 4; nt++) {
            int rg = bm + warp_m * 64 + mt * 16 + fr;
            int cg = bn + warp_n * 32 + nt * 8 + fk;
            float b0 = __ldg(bias + cg), b1 = __ldg(bias + cg + 1);
            float v00 = (acc[mt][nt][0] + b0) * scale;
            float v01 = (acc[mt][nt][1] + b1) * scale;
            float v10 = (acc[mt][nt][2] + b0) * scale;
            float v11 = (acc[mt][nt][3] + b1) * scale;
            __nv_bfloat16 h, l;
            __nv_bfloat162 hh, ll;
            split_bf16(v00, h, l); hh.x = h; ll.x = l;
            split_bf16(v01, h, l); hh.y = h; ll.y = l;
            *(__nv_bfloat162*)&Oh[(size_t)rg * DMODEL + cg] = hh;
            *(__nv_bfloat162*)&Ol[(size_t)rg * DMODEL + cg] = ll;
            split_bf16(v10, h, l); hh.x = h; ll.x = l;
            split_bf16(v11, h, l); hh.y = h; ll.y = l;
            *(__nv_bfloat162*)&Oh[(size_t)(rg + 8) * DMODEL + cg] = hh;
            *(__nv_bfloat162*)&Ol[(size_t)(rg + 8) * DMODEL + cg] = ll;
        }
    }
}

// ---------------------------------------------------------------------------
// HMMA flash attention with ldmatrix fragments.
// K AND V both loaded natively via cp.async; V B-frags via ldmatrix.trans.
// ---------------------------------------------------------------------------
#define VP 88   // bf16 row stride; 176B; ldmatrix conflict-free

__global__ __launch_bounds__(128)
void attn_mma(float* __restrict__ Out)
{
    __shared__ __nv_bfloat16 Kh[64][VP];
    __shared__ __nv_bfloat16 Kl[64][VP];
    __shared__ __nv_bfloat16 Vh[64][VP];
    __shared__ __nv_bfloat16 Vl[64][VP];

    const int tid = threadIdx.x;
    const int lane = tid & 31;
    const int wid = tid >> 5;
    const int b  = blockIdx.z;
    const int h  = blockIdx.y;
    const int q0 = blockIdx.x * 64;

    const int fr = lane >> 2;
    const int fk = (lane & 3) * 2;

    const __nv_bfloat16* __restrict__ Qh = g_Oh[0];
    const __nv_bfloat16* __restrict__ Ql = g_Ol[0];
    const __nv_bfloat16* __restrict__ Kgh = g_Oh[1];
    const __nv_bfloat16* __restrict__ Kgl = g_Ol[1];
    const __nv_bfloat16* __restrict__ Vgh = g_Oh[2];
    const __nv_bfloat16* __restrict__ Vgl = g_Ol[2];

    // loader: row = tid>>1 (0..63), half = tid&1 -> 4x16B per array
    const int lr = tid >> 1;
    const int lh = (tid & 1) * 32;
    const uint32_t aKh = smem_u32(&Kh[lr][lh]);
    const uint32_t aKl = smem_u32(&Kl[lr][lh]);
    const uint32_t aVh = smem_u32(&Vh[lr][lh]);
    const uint32_t aVl = smem_u32(&Vl[lr][lh]);

    const uint32_t bKh = smem_u32(Kh);
    const uint32_t bKl = smem_u32(Kl);
    const uint32_t bVh = smem_u32(Vh);
    const uint32_t bVl = smem_u32(Vl);

    // ldmatrix lane offsets
    //  A-frag (Q): row = wid*16 + (lane&15), col = (lane>>4)*8; per kc +32B
    const uint32_t qoff = ((wid * 16 + (lane & 15)) * VP + (lane >> 4) * 8) * 2;
    //  B-frag (K): n = pr*16 + (lane>>4)*8 + (lane&7), col = kc*16 + ((lane>>3)&1)*8
    const uint32_t koff = (((lane >> 4) * 8 + (lane & 7)) * VP + ((lane >> 3) & 1) * 8) * 2;
    //  B-frag (V, trans): crow = kc*16 + ((lane>>3)&1)*8 + (lane&7), dcol = pr*16 + (lane>>4)*8
    const uint32_t voff = ((((lane >> 3) & 1) * 8 + (lane & 7)) * VP + (lane >> 4) * 8) * 2;

    // ---- stage Q through Kh/Kl, extract fragments ----
    {
        const __nv_bfloat16* qh = Qh + ((size_t)(b * SQL + q0 + lr)) * DMODEL + h * HD_ + lh;
        const __nv_bfloat16* ql = Ql + ((size_t)(b * SQL + q0 + lr)) * DMODEL + h * HD_ + lh;
#pragma unroll
        for (int j = 0; j < 4; j++) {
            CP_ASYNC16(aKh + j * 16, qh + j * 8);
            CP_ASYNC16(aKl + j * 16, ql + j * 8);
        }
        CP_COMMIT();
        CP_WAIT0();
        __syncthreads();
    }
    uint32_t qfh[4][4], qfl[4][4];
#pragma unroll
    for (int kc = 0; kc < 4; kc++) {
        LDSM_X4(qfh[kc], bKh + qoff + kc * 32);
        LDSM_X4(qfl[kc], bKl + qoff + kc * 32);
    }
    __syncthreads();

    float m0 = -1e30f, m1 = -1e30f, l0 = 0.f, l1 = 0.f;
    float accO[8][4];
#pragma unroll
    for (int dt = 0; dt < 8; dt++)
#pragma unroll
        for (int r = 0; r < 4; r++) accO[dt][r] = 0.f;

    for (int t = 0; t < 8; t++) {
        const int k0 = t * 64;
        {
            const size_t rowoff = ((size_t)(b * SKL + k0 + lr)) * DMODEL + h * HD_ + lh;
            const __nv_bfloat16* kh = Kgh + rowoff;
            const __nv_bfloat16* kl = Kgl + rowoff;
            const __nv_bfloat16* vh = Vgh + rowoff;
            const __nv_bfloat16* vl = Vgl + rowoff;
#pragma unroll
            for (int j = 0; j < 4; j++) {
                CP_ASYNC16(aKh + j * 16, kh + j * 8);
                CP_ASYNC16(aKl + j * 16, kl + j * 8);
                CP_ASYNC16(aVh + j * 16, vh + j * 8);
                CP_ASYNC16(aVl + j * 16, vl + j * 8);
            }
            CP_COMMIT();
            CP_WAIT0();
        }
        __syncthreads();

        // ---- S = Q K^T ----
        float accS[8][4];
#pragma unroll
        for (int pr = 0; pr < 4; pr++) {
            uint32_t kh4[4][4], kl4[4][4];
#pragma unroll
            for (int kc = 0; kc < 4; kc++) {
                LDSM_X4(kh4[kc], bKh + koff + pr * (16 * VP * 2) + kc * 32);
                LDSM_X4(kl4[kc], bKl + koff + pr * (16 * VP * 2) + kc * 32);
            }
            int n0 = 2 * pr, n1 = 2 * pr + 1;
            accS[n0][0] = accS[n0][1] = accS[n0][2] = accS[n0][3] = 0.f;
            accS[n1][0] = accS[n1][1] = accS[n1][2] = accS[n1][3] = 0.f;
#pragma unroll
            for (int kc = 0; kc < 4; kc++) {
                mma16816(accS[n0], qfh[kc], &kh4[kc][0]);
                mma16816(accS[n0], qfh[kc], &kl4[kc][0]);
                mma16816(accS[n0], qfl[kc], &kh4[kc][0]);
                mma16816(accS[n1], qfh[kc], &kh4[kc][2]);
                mma16816(accS[n1], qfh[kc], &kl4[kc][2]);
                mma16816(accS[n1], qfl[kc], &kh4[kc][2]);
            }
        }

        // ---- online softmax (rows fr, fr+8) ----
        float mt0 = -1e30f, mt1 = -1e30f;
#pragma unroll
        for (int nt = 0; nt < 8; nt++) {
            mt0 = fmaxf(mt0, fmaxf(accS[nt][0], accS[nt][1]));
            mt1 = fmaxf(mt1, fmaxf(accS[nt][2], accS[nt][3]));
        }
        mt0 = fmaxf(mt0, __shfl_xor_sync(0xffffffffu, mt0, 1));
        mt0 = fmaxf(mt0, __shfl_xor_sync(0xffffffffu, mt0, 2));
        mt1 = fmaxf(mt1, __shfl_xor_sync(0xffffffffu, mt1, 1));
        mt1 = fmaxf(mt1, __shfl_xor_sync(0xffffffffu, mt1, 2));

        float mn0 = fmaxf(m0, mt0), mn1 = fmaxf(m1, mt1);
        float c0 = __expf(m0 - mn0), c1 = __expf(m1 - mn1);
        m0 = mn0; m1 = mn1;

        float s0 = 0.f, s1 = 0.f;
#pragma unroll
        for (int nt = 0; nt < 8; nt++) {
            accS[nt][0] = __expf(accS[nt][0] - mn0);
            accS[nt][1] = __expf(accS[nt][1] - mn0);
            accS[nt][2] = __expf(accS[nt][2] - mn1);
            accS[nt][3] = __expf(accS[nt][3] - mn1);
            s0 += accS[nt][0] + accS[nt][1];
            s1 += accS[nt][2] + accS[nt][3];
        }
        s0 += __shfl_xor_sync(0xffffffffu, s0, 1);
        s0 += __shfl_xor_sync(0xffffffffu, s0, 2);
        s1 += __shfl_xor_sync(0xffffffffu, s1, 1);
        s1 += __shfl_xor_sync(0xffffffffu, s1, 2);
        l0 = l0 * c0 + s0;
        l1 = l1 * c1 + s1;
#pragma unroll
        for (int dt = 0; dt < 8; dt++) {
            accO[dt][0] *= c0; accO[dt][1] *= c0;
            accO[dt][2] *= c1; accO[dt][3] *= c1;
        }

        // ---- P fragments in registers (hi/lo) ----
        uint32_t pfh[4][4], pfl[4][4];
#pragma unroll
        for (int kc = 0; kc < 4; kc++) {
            __nv_bfloat16 h00, l00, h01, l01;
            split_bf16(accS[2 * kc][0], h00, l00);
            split_bf16(accS[2 * kc][1], h01, l01);
            pfh[kc][0] = pack_bf2(h00, h01);
            pfl[kc][0] = pack_bf2(l00, l01);
            split_bf16(accS[2 * kc][2], h00, l00);
            split_bf16(accS[2 * kc][3], h01, l01);
            pfh[kc][1] = pack_bf2(h00, h01);
            pfl[kc][1] = pack_bf2(l00, l01);
            split_bf16(accS[2 * kc + 1][0], h00, l00);
            split_bf16(accS[2 * kc + 1][1], h01, l01);
            pfh[kc][2] = pack_bf2(h00, h01);
            pfl[kc][2] = pack_bf2(l00, l01);
            split_bf16(accS[2 * kc + 1][2], h00, l00);
            split_bf16(accS[2 * kc + 1][3], h01, l01);
            pfh[kc][3] = pack_bf2(h00, h01);
            pfl[kc][3] = pack_bf2(l00, l01);
        }

        // ---- O += P V  (V frags via ldmatrix.trans of natural-layout V) ----
#pragma unroll
        for (int pr = 0; pr < 4; pr++) {
            uint32_t vh4[4][4], vl4[4][4];
#pragma unroll
            for (int kc = 0; kc < 4; kc++) {
                LDSM_X4_T(vh4[kc], bVh + voff + kc * (16 * VP * 2) + pr * 32);
                LDSM_X4_T(vl4[kc], bVl + voff + kc * (16 * VP * 2) + pr * 32);
            }
            int d0 = 2 * pr, d1 = 2 * pr + 1;
#pragma unroll
            for (int kc = 0; kc < 4; kc++) {
                mma16816(accO[d0], pfh[kc], &vh4[kc][0]);
                mma16816(accO[d0], pfh[kc], &vl4[kc][0]);
                mma16816(accO[d0], pfl[kc], &vh4[kc][0]);
                mma16816(accO[d1], pfh[kc], &vh4[kc][2]);
                mma16816(accO[d1], pfh[kc], &vl4[kc][2]);
                mma16816(accO[d1], pfl[kc], &vh4[kc][2]);
            }
        }
        __syncthreads();
    }

    // ---- epilogue ----
    float inv0 = 1.f / l0, inv1 = 1.f / l1;
    int row0 = b * SQL + q0 + wid * 16 + fr;
#pragma unroll
    for (int dt = 0; dt < 8; dt++) {
        int col = h * HD_ + dt * 8 + fk;
        float2 o0 = { accO[dt][0] * inv0, accO[dt][1] * inv0 };
        float2 o1 = { accO[dt][2] * inv1, accO[dt][3] * inv1 };
        *(float2*)&Out[(size_t)row0 * DMODEL + col] = o0;
        *(float2*)&Out[(size_t)(row0 + 8) * DMODEL + col] = o1;
    }
}

// ---------------------------------------------------------------------------
extern "C" void kernel_launch(void* const* d_in, const int* in_sizes, int n_in,
                              void* d_out, int out_size)
{
    const float* hidden  = (const float*)d_in[0];
    const float* context = (const float*)d_in[1];
    const float* Wq = (const float*)d_in[2];
    const float* bq = (const float*)d_in[3];
    const float* Wk = (const float*)d_in[4];
    const float* bk = (const float*)d_in[5];
    const float* Wv = (const float*)d_in[6];
    const float* bv = (const float*)d_in[7];
    float* out = (float*)d_out;

    static __nv_bfloat16 *hh = nullptr, *hl = nullptr, *ch = nullptr, *cl = nullptr;
    if (!hh) {
        cudaGetSymbolAddress((void**)&hh, g_Hh);
        cudaGetSymbolAddress((void**)&hl, g_Hl);
        cudaGetSymbolAddress((void**)&ch, g_Ch);
        cudaGetSymbolAddress((void**)&cl, g_Cl);
        cudaFuncSetAttribute(proj_mma, cudaFuncAttributeMaxDynamicSharedMemorySize, PROJ_SMEM);
    }

    const int NEL = B_ * SQL * DMODEL;
    split_in<<<NEL / 4 / 256, 256>>>(hidden,  hh, hl);
    split_in<<<NEL / 4 / 256, 256>>>(context, ch, cl);

    dim3 tgrid(DMODEL / 32, DMODEL / 32, 3);
    transpose_w<<<tgrid, dim3(32, 8)>>>(Wq, Wk, Wv);

    dim3 pgrid(DMODEL / 128, (B_ * SQL) / 128);   // (6, 64)
    proj_mma<<<pgrid, 256, PROJ_SMEM>>>(hh, hl, bq, 0);
    proj_mma<<<pgrid, 256, PROJ_SMEM>>>(ch, cl, bk, 1);
    proj_mma<<<pgrid, 256, PROJ_SMEM>>>(ch, cl, bv, 2);

    dim3 agrid(SQL / 64, NH, B_);                 // (8, 12, 16)
    attn_mma<<<agrid, 128>>>(out);
}